// round 5
// baseline (speedup 1.0000x reference)
#include <cuda_runtime.h>
#include <cuda_bf16.h>
#include <math.h>

// ---------------- problem constants ----------------
#define M_TOK   16384            // 4 * 4096 tokens
#define DIMX    1024
#define HID     2048
#define NEXP    8
#define TOPK    2
#define RROWS   (M_TOK * TOPK)   // 32768 (token, slot) rows

// ---------------- device scratch (static .bss; no allocations) ----------------
__device__ float g_xn[(size_t)M_TOK * DIMX];              // tf32-rounded normalized activations
__device__ float g_h[(size_t)(RROWS + 128) * HID];        // SwiGLU output (tf32-rounded), +pad rows
__device__ float g_down[(size_t)RROWS * DIMX];            // down-proj per (token,slot), unweighted
__device__ float g_wup[(size_t)NEXP * 2 * HID * DIMX];    // tf32-rounded w_up
__device__ float g_wdn[(size_t)NEXP * DIMX * HID];        // tf32-rounded w_down
__device__ int   g_cnt[NEXP];
__device__ int   g_list[NEXP * M_TOK];                    // per-expert token lists
__device__ int   g_se[RROWS];                             // per (token,slot): expert id
__device__ int   g_sj[RROWS];                             // per (token,slot): index within expert list
__device__ float g_sw[RROWS];                             // per (token,slot): softmax weight

// ---------------- helpers ----------------
__device__ __forceinline__ float tf32r(float x) {
    unsigned u;
    asm("cvt.rna.tf32.f32 %0, %1;" : "=r"(u) : "f"(x));
    return __uint_as_float(u);
}
__device__ __forceinline__ unsigned sptr(const void* p) {
    return (unsigned)__cvta_generic_to_shared(p);
}
__device__ __forceinline__ void cp16(unsigned s, const void* g) {
    asm volatile("cp.async.ca.shared.global [%0], [%1], 16;" :: "r"(s), "l"(g));
}
__device__ __forceinline__ void cp_commit() { asm volatile("cp.async.commit_group;"); }

__device__ __forceinline__ void mma_tf32(float* c, const unsigned* a, const unsigned* b) {
    asm volatile(
        "mma.sync.aligned.m16n8k8.row.col.f32.tf32.tf32.f32 "
        "{%0,%1,%2,%3}, {%4,%5,%6,%7}, {%8,%9}, {%0,%1,%2,%3};"
        : "+f"(c[0]), "+f"(c[1]), "+f"(c[2]), "+f"(c[3])
        : "r"(a[0]), "r"(a[1]), "r"(a[2]), "r"(a[3]), "r"(b[0]), "r"(b[1]));
}

// ---------------- kernel 1: zero counters ----------------
__global__ void k_zero() {
    if (threadIdx.x < NEXP) g_cnt[threadIdx.x] = 0;
}

// ---------------- kernel 2: tf32-round weights (unbiased rna) ----------------
__global__ void k_prep(const float* __restrict__ wu, const float* __restrict__ wd) {
    int i = blockIdx.x * blockDim.x + threadIdx.x;
    int stride = gridDim.x * blockDim.x;
    const int NU = NEXP * 2 * HID * DIMX / 4;   // 8388608 float4
    const int ND = NEXP * DIMX * HID / 4;       // 4194304 float4
    const float4* u4 = (const float4*)wu;
    const float4* d4 = (const float4*)wd;
    float4* ou = (float4*)g_wup;
    float4* od = (float4*)g_wdn;
    for (int j = i; j < NU; j += stride) {
        float4 v = u4[j];
        v.x = tf32r(v.x); v.y = tf32r(v.y); v.z = tf32r(v.z); v.w = tf32r(v.w);
        ou[j] = v;
    }
    for (int j = i; j < ND; j += stride) {
        float4 v = d4[j];
        v.x = tf32r(v.x); v.y = tf32r(v.y); v.z = tf32r(v.z); v.w = tf32r(v.w);
        od[j] = v;
    }
}

// ---------------- kernel 3: RMSNorm + router + top2 + softmax + list build ----------------
__global__ void k_rms_router(const float* __restrict__ x,
                             const float* __restrict__ scale,
                             const float* __restrict__ wr) {
    __shared__ float sx[DIMX];
    __shared__ float sred[8];
    __shared__ float sscore[8];
    int t = blockIdx.x, tid = threadIdx.x;

    const float4* xr = (const float4*)(x + (size_t)t * DIMX);
    float4 v = xr[tid];
    float ss = v.x * v.x + v.y * v.y + v.z * v.z + v.w * v.w;
    #pragma unroll
    for (int o = 16; o; o >>= 1) ss += __shfl_xor_sync(0xffffffffu, ss, o);
    if ((tid & 31) == 0) sred[tid >> 5] = ss;
    __syncthreads();
    if (tid == 0) {
        float a = 0.f;
        #pragma unroll
        for (int i = 0; i < 8; i++) a += sred[i];
        sred[0] = a;
    }
    __syncthreads();
    float ms = sred[0] * (1.0f / (float)DIMX);
    float rs = rsqrtf(ms + 1e-6f);
    float4 sc = ((const float4*)scale)[tid];
    float4 xn;
    xn.x = v.x * sc.x * rs; xn.y = v.y * sc.y * rs;
    xn.z = v.z * sc.z * rs; xn.w = v.w * sc.w * rs;
    ((float4*)sx)[tid] = xn;                       // full-precision for router
    float4 xnr;
    xnr.x = tf32r(xn.x); xnr.y = tf32r(xn.y); xnr.z = tf32r(xn.z); xnr.w = tf32r(xn.w);
    ((float4*)(g_xn + (size_t)t * DIMX))[tid] = xnr;  // rounded for GEMM
    __syncthreads();

    // router: warp w computes score for expert w
    int w = tid >> 5, lane = tid & 31;
    const float* wrow = wr + w * DIMX;
    float acc = 0.f;
    #pragma unroll 8
    for (int j = lane; j < DIMX; j += 32) acc += sx[j] * __ldg(wrow + j);
    #pragma unroll
    for (int o = 16; o; o >>= 1) acc += __shfl_xor_sync(0xffffffffu, acc, o);
    if (lane == 0) sscore[w] = acc;
    __syncthreads();

    if (tid == 0) {
        float s0 = -1e30f; int i0 = 0;
        #pragma unroll
        for (int i = 0; i < 8; i++) { float s = sscore[i]; if (s > s0) { s0 = s; i0 = i; } }
        float s1 = -1e30f; int i1 = 0;
        #pragma unroll
        for (int i = 0; i < 8; i++) { if (i == i0) continue; float s = sscore[i]; if (s > s1) { s1 = s; i1 = i; } }
        float e1 = __expf(s1 - s0);
        float w0 = 1.f / (1.f + e1);
        float w1 = e1 * w0;
        int p0 = atomicAdd(&g_cnt[i0], 1);
        g_list[i0 * M_TOK + p0] = t;
        g_se[2 * t] = i0; g_sj[2 * t] = p0; g_sw[2 * t] = w0;
        int p1 = atomicAdd(&g_cnt[i1], 1);
        g_list[i1 * M_TOK + p1] = t;
        g_se[2 * t + 1] = i1; g_sj[2 * t + 1] = p1; g_sw[2 * t + 1] = w1;
    }
}

// ---------------- grouped GEMM tiles ----------------
#define ASTR 20        // smem row stride (floats): 20*g mod 32 -> 8 disjoint bank quads

// up: BM=128 rows, BN=64 u-cols + 64 gate-cols, BK=16, 256 threads (8 warps, 4x2)
#define BMU 128
#define BNU 64
#define KTU (DIMX / 16)   // 64 k-tiles

__global__ void __launch_bounds__(256, 2) k_up() {
    __shared__ float As[2][BMU * ASTR];
    __shared__ float Bs[2][2][BNU * ASTR];
    __shared__ int toks[BMU];
    int tid = threadIdx.x;

    // schedule: map blockIdx.x -> (expert, row-tile)
    int tile = blockIdx.x;
    int e = 0, off = 0, rt = 0, cnt_e = 0;
    bool found = false;
    for (e = 0; e < NEXP; e++) {
        int c = g_cnt[e];
        int nt = (c + BMU - 1) / BMU;
        if (tile < nt) { rt = tile; cnt_e = c; found = true; break; }
        tile -= nt; off += c;
    }
    if (!found) return;
    int valid = min(BMU, cnt_e - rt * BMU);
    int lbase = e * M_TOK + rt * BMU;
    int pbase = off + rt * BMU;
    int n0 = blockIdx.y * BNU;

    if (tid < BMU)
        toks[tid] = (tid < valid) ? g_list[lbase + tid] : g_list[lbase];
    __syncthreads();

    const float* WU = g_wup + (size_t)e * (2 * HID) * DIMX;
    int arow = tid >> 1, ac0 = (tid & 1) * 8;
    int bslab = tid >> 7, brr = (tid & 127) >> 1, bc0 = (tid & 1) * 8;
    const float* asrc = g_xn + (size_t)toks[arow] * DIMX;
    const float* bsrc = WU + (size_t)(bslab * HID + n0 + brr) * DIMX;

    auto issue = [&](int st, int k0) {
        cp16(sptr(&As[st][arow * ASTR + ac0]),            asrc + k0 + ac0);
        cp16(sptr(&As[st][arow * ASTR + ac0 + 4]),        asrc + k0 + ac0 + 4);
        cp16(sptr(&Bs[st][bslab][brr * ASTR + bc0]),      bsrc + k0 + bc0);
        cp16(sptr(&Bs[st][bslab][brr * ASTR + bc0 + 4]),  bsrc + k0 + bc0 + 4);
        cp_commit();
    };

    float acc[2][2][4][4] = {};   // [slab][mtile][ntile][frag]
    int w = tid >> 5, lane = tid & 31, g = lane >> 2, tg = lane & 3;
    int wm = (w >> 1) * 32, wn = (w & 1) * 32;

    issue(0, 0);
    for (int kt = 0; kt < KTU; kt++) {
        bool more = (kt + 1 < KTU);
        if (more) issue((kt + 1) & 1, (kt + 1) * 16);
        if (more) asm volatile("cp.async.wait_group 1;");
        else      asm volatile("cp.async.wait_group 0;");
        __syncthreads();
        int st = kt & 1;
        const float* A_ = As[st];
        const float* Bu = Bs[st][0];
        const float* Bg = Bs[st][1];
        #pragma unroll
        for (int ks = 0; ks < 2; ks++) {
            int c0 = ks * 8 + tg;
            unsigned a[2][4];
            #pragma unroll
            for (int mt = 0; mt < 2; mt++) {
                int r0 = wm + mt * 16 + g;
                a[mt][0] = __float_as_uint(A_[r0 * ASTR + c0]);
                a[mt][1] = __float_as_uint(A_[(r0 + 8) * ASTR + c0]);
                a[mt][2] = __float_as_uint(A_[r0 * ASTR + c0 + 4]);
                a[mt][3] = __float_as_uint(A_[(r0 + 8) * ASTR + c0 + 4]);
            }
            #pragma unroll
            for (int nt = 0; nt < 4; nt++) {
                int nn = wn + nt * 8 + g;
                unsigned bu[2] = { __float_as_uint(Bu[nn * ASTR + c0]),
                                   __float_as_uint(Bu[nn * ASTR + c0 + 4]) };
                unsigned bg[2] = { __float_as_uint(Bg[nn * ASTR + c0]),
                                   __float_as_uint(Bg[nn * ASTR + c0 + 4]) };
                #pragma unroll
                for (int mt = 0; mt < 2; mt++) {
                    mma_tf32(acc[0][mt][nt], a[mt], bu);
                    mma_tf32(acc[1][mt][nt], a[mt], bg);
                }
            }
        }
        __syncthreads();
    }

    // SwiGLU epilogue: h = u * silu(gate), tf32-rounded, compact layout
    #pragma unroll
    for (int mt = 0; mt < 2; mt++) {
        #pragma unroll
        for (int half = 0; half < 2; half++) {
            int r = wm + mt * 16 + g + half * 8;
            if (r < valid) {
                float* orow = g_h + (size_t)(pbase + r) * HID + n0 + wn;
                #pragma unroll
                for (int nt = 0; nt < 4; nt++) {
                    float u0 = acc[0][mt][nt][half * 2], u1 = acc[0][mt][nt][half * 2 + 1];
                    float q0 = acc[1][mt][nt][half * 2], q1 = acc[1][mt][nt][half * 2 + 1];
                    float h0 = u0 * (q0 / (1.f + __expf(-q0)));
                    float h1 = u1 * (q1 / (1.f + __expf(-q1)));
                    float2 hv = make_float2(tf32r(h0), tf32r(h1));
                    *(float2*)(orow + nt * 8 + 2 * tg) = hv;
                }
            }
        }
    }
}

// down: BM=128, BN=128, BK=16, K=2048, 256 threads (8 warps, 4x2, warp tile 32x64)
#define BMD 128
#define BND 128
#define KTD (HID / 16)   // 128 k-tiles

__global__ void __launch_bounds__(256, 2) k_down() {
    __shared__ float As[2][BMD * ASTR];
    __shared__ float Bs[2][BND * ASTR];
    int tid = threadIdx.x;

    int tile = blockIdx.x;
    int e = 0, off = 0, rt = 0, cnt_e = 0;
    bool found = false;
    for (e = 0; e < NEXP; e++) {
        int c = g_cnt[e];
        int nt = (c + BMD - 1) / BMD;
        if (tile < nt) { rt = tile; cnt_e = c; found = true; break; }
        tile -= nt; off += c;
    }
    if (!found) return;
    int valid = min(BMD, cnt_e - rt * BMD);
    int pbase = off + rt * BMD;
    int n0 = blockIdx.y * BND;

    const float* WD = g_wdn + (size_t)e * DIMX * HID;
    int arow = tid >> 1, ac0 = (tid & 1) * 8;
    const float* asrc = g_h + (size_t)(pbase + arow) * HID;   // padded rows cover overrun
    const float* bsrc = WD + (size_t)(n0 + arow) * HID;

    auto issue = [&](int st, int k0) {
        cp16(sptr(&As[st][arow * ASTR + ac0]),       asrc + k0 + ac0);
        cp16(sptr(&As[st][arow * ASTR + ac0 + 4]),   asrc + k0 + ac0 + 4);
        cp16(sptr(&Bs[st][arow * ASTR + ac0]),       bsrc + k0 + ac0);
        cp16(sptr(&Bs[st][arow * ASTR + ac0 + 4]),   bsrc + k0 + ac0 + 4);
        cp_commit();
    };

    float acc[2][8][4] = {};   // [mtile][ntile][frag]
    int w = tid >> 5, lane = tid & 31, g = lane >> 2, tg = lane & 3;
    int wm = (w >> 1) * 32, wn = (w & 1) * 64;

    issue(0, 0);
    for (int kt = 0; kt < KTD; kt++) {
        bool more = (kt + 1 < KTD);
        if (more) issue((kt + 1) & 1, (kt + 1) * 16);
        if (more) asm volatile("cp.async.wait_group 1;");
        else      asm volatile("cp.async.wait_group 0;");
        __syncthreads();
        int st = kt & 1;
        const float* A_ = As[st];
        const float* B_ = Bs[st];
        #pragma unroll
        for (int ks = 0; ks < 2; ks++) {
            int c0 = ks * 8 + tg;
            unsigned a[2][4];
            #pragma unroll
            for (int mt = 0; mt < 2; mt++) {
                int r0 = wm + mt * 16 + g;
                a[mt][0] = __float_as_uint(A_[r0 * ASTR + c0]);
                a[mt][1] = __float_as_uint(A_[(r0 + 8) * ASTR + c0]);
                a[mt][2] = __float_as_uint(A_[r0 * ASTR + c0 + 4]);
                a[mt][3] = __float_as_uint(A_[(r0 + 8) * ASTR + c0 + 4]);
            }
            #pragma unroll
            for (int nt = 0; nt < 8; nt++) {
                int nn = wn + nt * 8 + g;
                unsigned b[2] = { __float_as_uint(B_[nn * ASTR + c0]),
                                  __float_as_uint(B_[nn * ASTR + c0 + 4]) };
                #pragma unroll
                for (int mt = 0; mt < 2; mt++)
                    mma_tf32(acc[mt][nt], a[mt], b);
            }
        }
        __syncthreads();
    }

    #pragma unroll
    for (int mt = 0; mt < 2; mt++) {
        #pragma unroll
        for (int half = 0; half < 2; half++) {
            int r = wm + mt * 16 + g + half * 8;
            if (r < valid) {
                float* orow = g_down + (size_t)(pbase + r) * DIMX + n0 + wn;
                #pragma unroll
                for (int nt = 0; nt < 8; nt++) {
                    float2 hv = make_float2(acc[mt][nt][half * 2], acc[mt][nt][half * 2 + 1]);
                    *(float2*)(orow + nt * 8 + 2 * tg) = hv;
                }
            }
        }
    }
}

// ---------------- kernel 6: combine out = x + w0*down[p0] + w1*down[p1] ----------------
__global__ void k_combine(const float* __restrict__ x, float* __restrict__ out) {
    int t = blockIdx.x, tid = threadIdx.x;
    int e0 = g_se[2 * t], j0 = g_sj[2 * t];
    int e1 = g_se[2 * t + 1], j1 = g_sj[2 * t + 1];
    float w0 = g_sw[2 * t], w1 = g_sw[2 * t + 1];
    int off0 = 0, off1 = 0;
    #pragma unroll
    for (int i = 0; i < 8; i++) {
        int ci = __ldg(&g_cnt[i]);
        if (i < e0) off0 += ci;
        if (i < e1) off1 += ci;
    }
    int p0 = off0 + j0, p1 = off1 + j1;
    const float4* x4 = (const float4*)(x + (size_t)t * DIMX);
    const float4* d0 = (const float4*)(g_down + (size_t)p0 * DIMX);
    const float4* d1 = (const float4*)(g_down + (size_t)p1 * DIMX);
    float4 a = x4[tid], u = d0[tid], v = d1[tid];
    float4 o;
    o.x = a.x + w0 * u.x + w1 * v.x;
    o.y = a.y + w0 * u.y + w1 * v.y;
    o.z = a.z + w0 * u.z + w1 * v.z;
    o.w = a.w + w0 * u.w + w1 * v.w;
    ((float4*)(out + (size_t)t * DIMX))[tid] = o;
}

// ---------------- launch ----------------
extern "C" void kernel_launch(void* const* d_in, const int* in_sizes, int n_in,
                              void* d_out, int out_size) {
    const float* x     = (const float*)d_in[0];
    const float* scale = (const float*)d_in[1];
    const float* wr    = (const float*)d_in[2];
    const float* wu    = (const float*)d_in[3];
    const float* wd    = (const float*)d_in[4];
    float* out = (float*)d_out;

    k_zero<<<1, 32>>>();
    k_prep<<<2048, 256>>>(wu, wd);
    k_rms_router<<<M_TOK, 256>>>(x, scale, wr);
    // max row-tiles: sum ceil(cnt_e/128) <= 256 + 7 = 263 -> grid.x = 264
    k_up<<<dim3(264, HID / BNU), 256>>>();          // (264, 32)
    k_down<<<dim3(264, DIMX / BND), 256>>>();       // (264, 8)
    k_combine<<<M_TOK, 256>>>(x, out);
}

// round 8
// speedup vs baseline: 1.0476x; 1.0476x over previous
#include <cuda_runtime.h>
#include <cuda_fp16.h>
#include <math.h>
#include <cstdint>

// ---------------- problem constants ----------------
#define M_TOK   16384            // 4 * 4096 tokens
#define DIMX    1024
#define HID     2048
#define NEXP    8
#define TOPK    2
#define RROWS   (M_TOK * TOPK)   // 32768 (token, slot) rows

#define WSCALE   1024.0f         // weight pre-scale (exact power of 2)
#define IWSCALE  (1.0f / 1024.0f)

// ---------------- device scratch (static .bss; no allocations) ----------------
__device__ __half g_xn[(size_t)M_TOK * DIMX];             // fp16 normalized activations
__device__ __half g_h[(size_t)(RROWS + 128) * HID];       // fp16 SwiGLU output, +pad rows
__device__ float  g_down[(size_t)RROWS * DIMX];           // down-proj per (token,slot), unweighted
__device__ __half g_wup[(size_t)NEXP * 2 * HID * DIMX];   // fp16 w_up * 1024
__device__ __half g_wdn[(size_t)NEXP * DIMX * HID];       // fp16 w_down * 1024
__device__ int    g_cnt[NEXP];
__device__ int    g_list[NEXP * M_TOK];                   // per-expert token lists
__device__ int    g_se[RROWS];
__device__ int    g_sj[RROWS];
__device__ float  g_sw[RROWS];

// ---------------- helpers ----------------
__device__ __forceinline__ unsigned sptr(const void* p) {
    return (unsigned)__cvta_generic_to_shared(p);
}
__device__ __forceinline__ void cp16(unsigned s, const void* g) {
    asm volatile("cp.async.cg.shared.global [%0], [%1], 16;" :: "r"(s), "l"(g));
}
__device__ __forceinline__ void cp_commit() { asm volatile("cp.async.commit_group;"); }

// fp16 MMA, f32 accumulate: D(16x8) += A(16x16) * B(16x8)
__device__ __forceinline__ void mma_f16(float* c, const uint32_t* a, uint32_t b0, uint32_t b1) {
    asm volatile(
        "mma.sync.aligned.m16n8k16.row.col.f32.f16.f16.f32 "
        "{%0,%1,%2,%3}, {%4,%5,%6,%7}, {%8,%9}, {%0,%1,%2,%3};"
        : "+f"(c[0]), "+f"(c[1]), "+f"(c[2]), "+f"(c[3])
        : "r"(a[0]), "r"(a[1]), "r"(a[2]), "r"(a[3]), "r"(b0), "r"(b1));
}

// ---------------- GEMM geometry ----------------
// block tile: 128(M) x 256(N), BK=16, 256 threads = 8 warps as 2(M) x 4(N), warp tile 64x64
#define BK      16
#define ASTRH   24                       // smem halves per 16-half row (48B, padded)
#define STG_H   9216                     // halves per stage: (128+256)*24
#define SB_OFF  3072                     // B tile offset within stage (halves): 128*24
#define STAGES  4
#define TOKS_H  (STAGES * STG_H)         // toks array after 4 stages (half-index)
#define SMEM_TOT (STAGES * STG_H * 2 + 512)

// ---------------- kernel 1: zero counters ----------------
__global__ void k_zero() {
    if (threadIdx.x < NEXP) g_cnt[threadIdx.x] = 0;
}

// ---------------- kernel 2: convert weights to fp16 * 1024 ----------------
__global__ void k_prep(const float* __restrict__ wu, const float* __restrict__ wd) {
    int i = blockIdx.x * blockDim.x + threadIdx.x;
    int stride = gridDim.x * blockDim.x;
    const int NU = NEXP * 2 * HID * DIMX / 4;
    const int ND = NEXP * DIMX * HID / 4;
    const float4* u4 = (const float4*)wu;
    const float4* d4 = (const float4*)wd;
    for (int j = i; j < NU; j += stride) {
        float4 v = u4[j];
        __half2* o = (__half2*)(g_wup + (size_t)j * 4);
        o[0] = __floats2half2_rn(v.x * WSCALE, v.y * WSCALE);
        o[1] = __floats2half2_rn(v.z * WSCALE, v.w * WSCALE);
    }
    for (int j = i; j < ND; j += stride) {
        float4 v = d4[j];
        __half2* o = (__half2*)(g_wdn + (size_t)j * 4);
        o[0] = __floats2half2_rn(v.x * WSCALE, v.y * WSCALE);
        o[1] = __floats2half2_rn(v.z * WSCALE, v.w * WSCALE);
    }
}

// ---------------- kernel 3: RMSNorm + router + top2 + softmax + list build ----------------
__global__ void k_rms_router(const float* __restrict__ x,
                             const float* __restrict__ scale,
                             const float* __restrict__ wr) {
    __shared__ float sx[DIMX];
    __shared__ float sred[8];
    __shared__ float sscore[8];
    int t = blockIdx.x, tid = threadIdx.x;

    const float4* xr = (const float4*)(x + (size_t)t * DIMX);
    float4 v = xr[tid];
    float ss = v.x * v.x + v.y * v.y + v.z * v.z + v.w * v.w;
    #pragma unroll
    for (int o = 16; o; o >>= 1) ss += __shfl_xor_sync(0xffffffffu, ss, o);
    if ((tid & 31) == 0) sred[tid >> 5] = ss;
    __syncthreads();
    if (tid == 0) {
        float a = 0.f;
        #pragma unroll
        for (int i = 0; i < 8; i++) a += sred[i];
        sred[0] = a;
    }
    __syncthreads();
    float ms = sred[0] * (1.0f / (float)DIMX);
    float rs = rsqrtf(ms + 1e-6f);
    float4 sc = ((const float4*)scale)[tid];
    float4 xn;
    xn.x = v.x * sc.x * rs; xn.y = v.y * sc.y * rs;
    xn.z = v.z * sc.z * rs; xn.w = v.w * sc.w * rs;
    ((float4*)sx)[tid] = xn;                       // full precision for router
    __half2* hp = (__half2*)(g_xn + (size_t)t * DIMX + 4 * tid);
    hp[0] = __floats2half2_rn(xn.x, xn.y);
    hp[1] = __floats2half2_rn(xn.z, xn.w);
    __syncthreads();

    int w = tid >> 5, lane = tid & 31;
    const float* wrow = wr + w * DIMX;
    float acc = 0.f;
    #pragma unroll 8
    for (int j = lane; j < DIMX; j += 32) acc += sx[j] * __ldg(wrow + j);
    #pragma unroll
    for (int o = 16; o; o >>= 1) acc += __shfl_xor_sync(0xffffffffu, acc, o);
    if (lane == 0) sscore[w] = acc;
    __syncthreads();

    if (tid == 0) {
        float s0 = -1e30f; int i0 = 0;
        #pragma unroll
        for (int i = 0; i < 8; i++) { float s = sscore[i]; if (s > s0) { s0 = s; i0 = i; } }
        float s1 = -1e30f; int i1 = 0;
        #pragma unroll
        for (int i = 0; i < 8; i++) { if (i == i0) continue; float s = sscore[i]; if (s > s1) { s1 = s; i1 = i; } }
        float e1 = __expf(s1 - s0);
        float w0 = 1.f / (1.f + e1);
        float w1 = e1 * w0;
        int p0 = atomicAdd(&g_cnt[i0], 1);
        g_list[i0 * M_TOK + p0] = t;
        g_se[2 * t] = i0; g_sj[2 * t] = p0; g_sw[2 * t] = w0;
        int p1 = atomicAdd(&g_cnt[i1], 1);
        g_list[i1 * M_TOK + p1] = t;
        g_se[2 * t + 1] = i1; g_sj[2 * t + 1] = p1; g_sw[2 * t + 1] = w1;
    }
}

// ---------------- scheduling: blockIdx.y -> (expert, row-tile) ----------------
struct Sched { int e, rt, valid, pbase; bool ok; };
__device__ __forceinline__ Sched sched_rowtile(int tile) {
    Sched s; s.ok = false;
    int off = 0;
    for (int e = 0; e < NEXP; e++) {
        int c = g_cnt[e];
        int nt = (c + 127) >> 7;
        if (tile < nt) {
            s.e = e; s.rt = tile;
            s.valid = min(128, c - tile * 128);
            s.pbase = off + tile * 128;
            s.ok = true;
            return s;
        }
        tile -= nt; off += c;
    }
    return s;
}

// ---------------- kernel 4: up GEMM (fp16 mma, 128x256 block = 128u + 128gate cols) ----------------
#define KTU (DIMX / BK)   // 64

__global__ void __launch_bounds__(256) k_up() {
    extern __shared__ __half smem[];
    int tid = threadIdx.x, wid = tid >> 5, lane = tid & 31;
    int g = lane >> 2, tg = lane & 3;

    Sched sc = sched_rowtile(blockIdx.y);
    if (!sc.ok) return;
    int c0 = blockIdx.x * 128;          // u/gate column base within HID
    int lbase = sc.e * M_TOK + sc.rt * 128;

    int* toks = (int*)(smem + TOKS_H);
    if (tid < 128)
        toks[tid] = (tid < sc.valid) ? g_list[lbase + tid] : g_list[lbase];
    __syncthreads();

    // loader setup: A -> thread t loads row t>>1, chunk t&1 (16B); B -> row t, 2 chunks
    const __half* a_src = g_xn + (size_t)toks[tid >> 1] * DIMX + (tid & 1) * 8;
    uint32_t a_dst = sptr(smem) + ((tid >> 1) * ASTRH + (tid & 1) * 8) * 2;
    int br = tid, q = br >> 6, j = br & 63;
    const __half* WU = g_wup + (size_t)sc.e * 2 * HID * DIMX;
    int brow = (j < 32) ? (c0 + q * 32 + j) : (HID + c0 + q * 32 + (j - 32));
    const __half* b_src = WU + (size_t)brow * DIMX;
    uint32_t b_dst = sptr(smem) + (SB_OFF + br * ASTRH) * 2;

    auto load_tile = [&](int ti) {
        uint32_t so = (uint32_t)(ti & (STAGES - 1)) * (STG_H * 2);
        const __half* ap = a_src + ti * BK;
        const __half* bp = b_src + ti * BK;
        cp16(a_dst + so, ap);
        cp16(b_dst + so, bp);
        cp16(b_dst + so + 16, bp + 8);   // FIXED: halves [8,16) live at byte +16, not +32
    };

    load_tile(0); cp_commit();
    load_tile(1); cp_commit();
    load_tile(2); cp_commit();

    float acc[4][8][4] = {};
    int wm = (wid >> 2) * 64, wq = wid & 3;
    int nbase = wq * 64;

    for (int kt = 0; kt < KTU; kt++) {
        if (kt + 3 < KTU) load_tile(kt + 3);
        cp_commit();
        asm volatile("cp.async.wait_group 3;");
        __syncthreads();
        const __half* S = smem + (kt & (STAGES - 1)) * STG_H;
        uint32_t a[4][4];
        #pragma unroll
        for (int mt = 0; mt < 4; mt++) {
            int m0 = wm + mt * 16 + g;
            a[mt][0] = *(const uint32_t*)&S[m0 * ASTRH + 2 * tg];
            a[mt][1] = *(const uint32_t*)&S[(m0 + 8) * ASTRH + 2 * tg];
            a[mt][2] = *(const uint32_t*)&S[m0 * ASTRH + 2 * tg + 8];
            a[mt][3] = *(const uint32_t*)&S[(m0 + 8) * ASTRH + 2 * tg + 8];
        }
        #pragma unroll
        for (int nt = 0; nt < 8; nt++) {
            int bo = SB_OFF + (nbase + nt * 8 + g) * ASTRH + 2 * tg;
            uint32_t b0 = *(const uint32_t*)&S[bo];
            uint32_t b1 = *(const uint32_t*)&S[bo + 8];
            #pragma unroll
            for (int mt = 0; mt < 4; mt++)
                mma_f16(acc[mt][nt], a[mt], b0, b1);
        }
        __syncthreads();
    }

    // SwiGLU epilogue: warp quarter q covers u cols [c0+q*32, +32) in nt 0..3, gate in nt 4..7
    #pragma unroll
    for (int mt = 0; mt < 4; mt++) {
        #pragma unroll
        for (int hf = 0; hf < 2; hf++) {
            int r = wm + mt * 16 + g + hf * 8;
            if (r < sc.valid) {
                __half* orow = g_h + (size_t)(sc.pbase + r) * HID;
                #pragma unroll
                for (int nt = 0; nt < 4; nt++) {
                    int ch = c0 + wq * 32 + nt * 8 + 2 * tg;
                    float u0 = acc[mt][nt][hf * 2]     * IWSCALE;
                    float u1 = acc[mt][nt][hf * 2 + 1] * IWSCALE;
                    float q0 = acc[mt][nt + 4][hf * 2]     * IWSCALE;
                    float q1 = acc[mt][nt + 4][hf * 2 + 1] * IWSCALE;
                    float h0 = u0 * (q0 / (1.f + __expf(-q0)));
                    float h1 = u1 * (q1 / (1.f + __expf(-q1)));
                    *(__half2*)(orow + ch) = __floats2half2_rn(h0, h1);
                }
            }
        }
    }
}

// ---------------- kernel 5: down GEMM (fp16 mma, 128x256 block, K=2048) ----------------
#define KTD (HID / BK)    // 128

__global__ void __launch_bounds__(256) k_down() {
    extern __shared__ __half smem[];
    int tid = threadIdx.x, wid = tid >> 5, lane = tid & 31;
    int g = lane >> 2, tg = lane & 3;

    Sched sc = sched_rowtile(blockIdx.y);
    if (!sc.ok) return;
    int n0 = blockIdx.x * 256;

    const __half* a_src = g_h + (size_t)(sc.pbase + (tid >> 1)) * HID + (tid & 1) * 8;
    uint32_t a_dst = sptr(smem) + ((tid >> 1) * ASTRH + (tid & 1) * 8) * 2;
    const __half* WD = g_wdn + (size_t)sc.e * DIMX * HID;
    const __half* b_src = WD + (size_t)(n0 + tid) * HID;
    uint32_t b_dst = sptr(smem) + (SB_OFF + tid * ASTRH) * 2;

    auto load_tile = [&](int ti) {
        uint32_t so = (uint32_t)(ti & (STAGES - 1)) * (STG_H * 2);
        const __half* ap = a_src + ti * BK;
        const __half* bp = b_src + ti * BK;
        cp16(a_dst + so, ap);
        cp16(b_dst + so, bp);
        cp16(b_dst + so + 16, bp + 8);   // FIXED: halves [8,16) live at byte +16, not +32
    };

    load_tile(0); cp_commit();
    load_tile(1); cp_commit();
    load_tile(2); cp_commit();

    float acc[4][8][4] = {};
    int wm = (wid >> 2) * 64, wq = wid & 3;
    int nbase = wq * 64;

    for (int kt = 0; kt < KTD; kt++) {
        if (kt + 3 < KTD) load_tile(kt + 3);
        cp_commit();
        asm volatile("cp.async.wait_group 3;");
        __syncthreads();
        const __half* S = smem + (kt & (STAGES - 1)) * STG_H;
        uint32_t a[4][4];
        #pragma unroll
        for (int mt = 0; mt < 4; mt++) {
            int m0 = wm + mt * 16 + g;
            a[mt][0] = *(const uint32_t*)&S[m0 * ASTRH + 2 * tg];
            a[mt][1] = *(const uint32_t*)&S[(m0 + 8) * ASTRH + 2 * tg];
            a[mt][2] = *(const uint32_t*)&S[m0 * ASTRH + 2 * tg + 8];
            a[mt][3] = *(const uint32_t*)&S[(m0 + 8) * ASTRH + 2 * tg + 8];
        }
        #pragma unroll
        for (int nt = 0; nt < 8; nt++) {
            int bo = SB_OFF + (nbase + nt * 8 + g) * ASTRH + 2 * tg;
            uint32_t b0 = *(const uint32_t*)&S[bo];
            uint32_t b1 = *(const uint32_t*)&S[bo + 8];
            #pragma unroll
            for (int mt = 0; mt < 4; mt++)
                mma_f16(acc[mt][nt], a[mt], b0, b1);
        }
        __syncthreads();
    }

    #pragma unroll
    for (int mt = 0; mt < 4; mt++) {
        #pragma unroll
        for (int hf = 0; hf < 2; hf++) {
            int r = wm + mt * 16 + g + hf * 8;
            if (r < sc.valid) {
                float* orow = g_down + (size_t)(sc.pbase + r) * DIMX + n0;
                #pragma unroll
                for (int nt = 0; nt < 8; nt++) {
                    int cc = nbase + nt * 8 + 2 * tg;
                    float2 v;
                    v.x = acc[mt][nt][hf * 2]     * IWSCALE;
                    v.y = acc[mt][nt][hf * 2 + 1] * IWSCALE;
                    *(float2*)(orow + cc) = v;
                }
            }
        }
    }
}

// ---------------- kernel 6: combine out = x + w0*down[p0] + w1*down[p1] ----------------
__global__ void k_combine(const float* __restrict__ x, float* __restrict__ out) {
    int t = blockIdx.x, tid = threadIdx.x;
    int e0 = g_se[2 * t], j0 = g_sj[2 * t];
    int e1 = g_se[2 * t + 1], j1 = g_sj[2 * t + 1];
    float w0 = g_sw[2 * t], w1 = g_sw[2 * t + 1];
    int off0 = 0, off1 = 0;
    #pragma unroll
    for (int i = 0; i < 8; i++) {
        int ci = __ldg(&g_cnt[i]);
        if (i < e0) off0 += ci;
        if (i < e1) off1 += ci;
    }
    int p0 = off0 + j0, p1 = off1 + j1;
    const float4* x4 = (const float4*)(x + (size_t)t * DIMX);
    const float4* d0 = (const float4*)(g_down + (size_t)p0 * DIMX);
    const float4* d1 = (const float4*)(g_down + (size_t)p1 * DIMX);
    float4 a = x4[tid], u = d0[tid], v = d1[tid];
    float4 o;
    o.x = a.x + w0 * u.x + w1 * v.x;
    o.y = a.y + w0 * u.y + w1 * v.y;
    o.z = a.z + w0 * u.z + w1 * v.z;
    o.w = a.w + w0 * u.w + w1 * v.w;
    ((float4*)(out + (size_t)t * DIMX))[tid] = o;
}

// ---------------- launch ----------------
extern "C" void kernel_launch(void* const* d_in, const int* in_sizes, int n_in,
                              void* d_out, int out_size) {
    const float* x     = (const float*)d_in[0];
    const float* scale = (const float*)d_in[1];
    const float* wr    = (const float*)d_in[2];
    const float* wu    = (const float*)d_in[3];
    const float* wd    = (const float*)d_in[4];
    float* out = (float*)d_out;

    cudaFuncSetAttribute(k_up,   cudaFuncAttributeMaxDynamicSharedMemorySize, SMEM_TOT);
    cudaFuncSetAttribute(k_down, cudaFuncAttributeMaxDynamicSharedMemorySize, SMEM_TOT);

    k_zero<<<1, 32>>>();
    k_prep<<<2048, 256>>>(wu, wd);
    k_rms_router<<<M_TOK, 256>>>(x, scale, wr);
    // grid: x = n-tile (fast: a wave shares A row-tile, keeps B in L2), y = row-tile (264 >= 263 worst case)
    k_up  <<<dim3(HID / 128, 264), 256, SMEM_TOT>>>();   // (16, 264)
    k_down<<<dim3(DIMX / 256, 264), 256, SMEM_TOT>>>();  // (4, 264)
    k_combine<<<M_TOK, 256>>>(x, out);
}

// round 9
// speedup vs baseline: 1.9372x; 1.8491x over previous
#include <cuda_runtime.h>
#include <cuda_fp16.h>
#include <math.h>
#include <cstdint>

// ---------------- problem constants ----------------
#define M_TOK   16384            // 4 * 4096 tokens
#define DIMX    1024
#define HID     2048
#define NEXP    8
#define TOPK    2
#define RROWS   (M_TOK * TOPK)   // 32768 (token, slot) rows

#define WSCALE   1024.0f         // weight pre-scale (exact power of 2)
#define IWSCALE  (1.0f / 1024.0f)

// ---------------- device scratch (static .bss; no allocations) ----------------
__device__ __half g_xn[(size_t)M_TOK * DIMX];             // fp16 normalized activations
__device__ __half g_h[(size_t)(RROWS + 128) * HID];       // fp16 SwiGLU output, +pad rows
__device__ float  g_down[(size_t)RROWS * DIMX];           // down-proj per (token,slot), unweighted
__device__ __half g_wup[(size_t)NEXP * 2 * HID * DIMX];   // fp16 w_up * 1024
__device__ __half g_wdn[(size_t)NEXP * DIMX * HID];       // fp16 w_down * 1024
__device__ int    g_cnt[NEXP];
__device__ int    g_list[NEXP * M_TOK];                   // per-expert token lists
__device__ int    g_se[RROWS];
__device__ int    g_sj[RROWS];
__device__ float  g_sw[RROWS];

// ---------------- helpers ----------------
__device__ __forceinline__ unsigned sptr(const void* p) {
    return (unsigned)__cvta_generic_to_shared(p);
}
__device__ __forceinline__ void cp16(unsigned s, const void* g) {
    asm volatile("cp.async.cg.shared.global [%0], [%1], 16;" :: "r"(s), "l"(g));
}
__device__ __forceinline__ void cp_commit() { asm volatile("cp.async.commit_group;"); }

// fp16 MMA, f32 accumulate: D(16x8) += A(16x16) * B(16x8)
__device__ __forceinline__ void mma_f16(float* c, const uint32_t* a, uint32_t b0, uint32_t b1) {
    asm volatile(
        "mma.sync.aligned.m16n8k16.row.col.f32.f16.f16.f32 "
        "{%0,%1,%2,%3}, {%4,%5,%6,%7}, {%8,%9}, {%0,%1,%2,%3};"
        : "+f"(c[0]), "+f"(c[1]), "+f"(c[2]), "+f"(c[3])
        : "r"(a[0]), "r"(a[1]), "r"(a[2]), "r"(a[3]), "r"(b0), "r"(b1));
}

// ---------------- GEMM geometry ----------------
// block tile 128(M) x 256(N), BK=32, 512 threads = 16 warps as 2(M) x 8(N), warp tile 64x32
#define BK      32
#define ASTRH   40                        // smem halves per 32-half row (80B padded); 5g mod 8 perm -> conflict-free reads
#define STG_H   (384 * ASTRH)             // halves per stage: (128+256)*40 = 15360
#define STG_B   (STG_H * 2)               // 30720 bytes
#define SB_OFF  (128 * ASTRH)             // B tile offset within stage (halves) = 5120
#define STAGES  4
#define TOKS_H  (STAGES * STG_H)          // toks array after 4 stages (half index)
#define SMEM_TOT (TOKS_H * 2 + 512)       // 123392 bytes

// ---------------- kernel 1: zero counters ----------------
__global__ void k_zero() {
    if (threadIdx.x < NEXP) g_cnt[threadIdx.x] = 0;
}

// ---------------- kernel 2: convert weights to fp16 * 1024 ----------------
__global__ void k_prep(const float* __restrict__ wu, const float* __restrict__ wd) {
    int i = blockIdx.x * blockDim.x + threadIdx.x;
    int stride = gridDim.x * blockDim.x;
    const int NU = NEXP * 2 * HID * DIMX / 4;
    const int ND = NEXP * DIMX * HID / 4;
    const float4* u4 = (const float4*)wu;
    const float4* d4 = (const float4*)wd;
    for (int j = i; j < NU; j += stride) {
        float4 v = u4[j];
        __half2* o = (__half2*)(g_wup + (size_t)j * 4);
        o[0] = __floats2half2_rn(v.x * WSCALE, v.y * WSCALE);
        o[1] = __floats2half2_rn(v.z * WSCALE, v.w * WSCALE);
    }
    for (int j = i; j < ND; j += stride) {
        float4 v = d4[j];
        __half2* o = (__half2*)(g_wdn + (size_t)j * 4);
        o[0] = __floats2half2_rn(v.x * WSCALE, v.y * WSCALE);
        o[1] = __floats2half2_rn(v.z * WSCALE, v.w * WSCALE);
    }
}

// ---------------- kernel 3: RMSNorm + router + top2 + softmax + list build ----------------
__global__ void k_rms_router(const float* __restrict__ x,
                             const float* __restrict__ scale,
                             const float* __restrict__ wr) {
    __shared__ float sx[DIMX];
    __shared__ float sred[8];
    __shared__ float sscore[8];
    int t = blockIdx.x, tid = threadIdx.x;

    const float4* xr = (const float4*)(x + (size_t)t * DIMX);
    float4 v = xr[tid];
    float ss = v.x * v.x + v.y * v.y + v.z * v.z + v.w * v.w;
    #pragma unroll
    for (int o = 16; o; o >>= 1) ss += __shfl_xor_sync(0xffffffffu, ss, o);
    if ((tid & 31) == 0) sred[tid >> 5] = ss;
    __syncthreads();
    if (tid == 0) {
        float a = 0.f;
        #pragma unroll
        for (int i = 0; i < 8; i++) a += sred[i];
        sred[0] = a;
    }
    __syncthreads();
    float ms = sred[0] * (1.0f / (float)DIMX);
    float rs = rsqrtf(ms + 1e-6f);
    float4 sc = ((const float4*)scale)[tid];
    float4 xn;
    xn.x = v.x * sc.x * rs; xn.y = v.y * sc.y * rs;
    xn.z = v.z * sc.z * rs; xn.w = v.w * sc.w * rs;
    ((float4*)sx)[tid] = xn;                       // full precision for router
    __half2* hp = (__half2*)(g_xn + (size_t)t * DIMX + 4 * tid);
    hp[0] = __floats2half2_rn(xn.x, xn.y);
    hp[1] = __floats2half2_rn(xn.z, xn.w);
    __syncthreads();

    int w = tid >> 5, lane = tid & 31;
    const float* wrow = wr + w * DIMX;
    float acc = 0.f;
    #pragma unroll 8
    for (int j = lane; j < DIMX; j += 32) acc += sx[j] * __ldg(wrow + j);
    #pragma unroll
    for (int o = 16; o; o >>= 1) acc += __shfl_xor_sync(0xffffffffu, acc, o);
    if (lane == 0) sscore[w] = acc;
    __syncthreads();

    if (tid == 0) {
        float s0 = -1e30f; int i0 = 0;
        #pragma unroll
        for (int i = 0; i < 8; i++) { float s = sscore[i]; if (s > s0) { s0 = s; i0 = i; } }
        float s1 = -1e30f; int i1 = 0;
        #pragma unroll
        for (int i = 0; i < 8; i++) { if (i == i0) continue; float s = sscore[i]; if (s > s1) { s1 = s; i1 = i; } }
        float e1 = __expf(s1 - s0);
        float w0 = 1.f / (1.f + e1);
        float w1 = e1 * w0;
        int p0 = atomicAdd(&g_cnt[i0], 1);
        g_list[i0 * M_TOK + p0] = t;
        g_se[2 * t] = i0; g_sj[2 * t] = p0; g_sw[2 * t] = w0;
        int p1 = atomicAdd(&g_cnt[i1], 1);
        g_list[i1 * M_TOK + p1] = t;
        g_se[2 * t + 1] = i1; g_sj[2 * t + 1] = p1; g_sw[2 * t + 1] = w1;
    }
}

// ---------------- scheduling: blockIdx.y -> (expert, row-tile) ----------------
struct Sched { int e, rt, valid, pbase; bool ok; };
__device__ __forceinline__ Sched sched_rowtile(int tile) {
    Sched s; s.ok = false;
    int off = 0;
    for (int e = 0; e < NEXP; e++) {
        int c = g_cnt[e];
        int nt = (c + 127) >> 7;
        if (tile < nt) {
            s.e = e; s.rt = tile;
            s.valid = min(128, c - tile * 128);
            s.pbase = off + tile * 128;
            s.ok = true;
            return s;
        }
        tile -= nt; off += c;
    }
    return s;
}

// ---------------- kernel 4: up GEMM (fp16 mma, 128x256 block; per warp 16 HID cols u+gate) ----------------
#define KTU (DIMX / BK)   // 32

__global__ void __launch_bounds__(512) k_up() {
    extern __shared__ __half smem[];
    int tid = threadIdx.x, wid = tid >> 5, lane = tid & 31;
    int g = lane >> 2, tg = lane & 3;

    Sched sc = sched_rowtile(blockIdx.y);
    if (!sc.ok) return;
    int c0 = blockIdx.x * 128;          // u/gate column base within HID
    int lbase = sc.e * M_TOK + sc.rt * 128;

    int* toks = (int*)(smem + TOKS_H);
    if (tid < 128)
        toks[tid] = (tid < sc.valid) ? g_list[lbase + tid] : g_list[lbase];
    __syncthreads();

    // A loader: thread t -> row t>>2, 16B chunk t&3
    int arow = tid >> 2, ac = tid & 3;
    const __half* a_src = g_xn + (size_t)toks[arow] * DIMX + ac * 8;
    uint32_t a_dst = sptr(smem) + (arow * ASTRH + ac * 8) * 2;
    // B loader: thread t -> block row t>>1, 32B half-pair t&1.
    // Block B row br = w8*32 + j:  j<16 -> u col c0+w8*16+j ; j>=16 -> gate col c0+w8*16+(j-16)
    int br = tid >> 1, w8 = br >> 5, j = br & 31;
    int bhid = c0 + w8 * 16 + (j & 15);
    int brow = (j < 16) ? bhid : (HID + bhid);
    const __half* WU = g_wup + (size_t)sc.e * 2 * HID * DIMX;
    const __half* b_src = WU + (size_t)brow * DIMX + (tid & 1) * 16;
    uint32_t b_dst = sptr(smem) + (SB_OFF + br * ASTRH + (tid & 1) * 16) * 2;

    auto load_tile = [&](int ti) {
        uint32_t so = (uint32_t)(ti & (STAGES - 1)) * STG_B;
        cp16(a_dst + so, a_src + ti * BK);
        cp16(b_dst + so, b_src + ti * BK);
        cp16(b_dst + so + 16, b_src + ti * BK + 8);
    };

    load_tile(0); cp_commit();
    load_tile(1); cp_commit();
    load_tile(2); cp_commit();

    float acc[4][4][4] = {};
    int wm = (wid >> 3) * 64, wq = wid & 7;

    for (int kt = 0; kt < KTU; kt++) {
        if (kt + 3 < KTU) load_tile(kt + 3);
        cp_commit();
        asm volatile("cp.async.wait_group 3;");
        __syncthreads();
        const __half* S = smem + (kt & (STAGES - 1)) * STG_H;
        #pragma unroll
        for (int ks = 0; ks < 2; ks++) {
            int ko = ks * 16;
            uint32_t a[4][4];
            #pragma unroll
            for (int mt = 0; mt < 4; mt++) {
                int m0 = wm + mt * 16 + g;
                a[mt][0] = *(const uint32_t*)&S[m0 * ASTRH + ko + 2 * tg];
                a[mt][1] = *(const uint32_t*)&S[(m0 + 8) * ASTRH + ko + 2 * tg];
                a[mt][2] = *(const uint32_t*)&S[m0 * ASTRH + ko + 2 * tg + 8];
                a[mt][3] = *(const uint32_t*)&S[(m0 + 8) * ASTRH + ko + 2 * tg + 8];
            }
            #pragma unroll
            for (int nt = 0; nt < 4; nt++) {
                int nr = wq * 32 + nt * 8 + g;
                uint32_t b0 = *(const uint32_t*)&S[SB_OFF + nr * ASTRH + ko + 2 * tg];
                uint32_t b1 = *(const uint32_t*)&S[SB_OFF + nr * ASTRH + ko + 2 * tg + 8];
                #pragma unroll
                for (int mt = 0; mt < 4; mt++)
                    mma_f16(acc[mt][nt], a[mt], b0, b1);
            }
        }
        __syncthreads();
    }

    // SwiGLU: warp covers HID cols [c0+wq*16, +16); nt 0..1 = u, nt 2..3 = gate (same cols)
    int ch0 = c0 + wq * 16;
    #pragma unroll
    for (int mt = 0; mt < 4; mt++) {
        #pragma unroll
        for (int hf = 0; hf < 2; hf++) {
            int r = wm + mt * 16 + g + hf * 8;
            if (r < sc.valid) {
                __half* orow = g_h + (size_t)(sc.pbase + r) * HID;
                #pragma unroll
                for (int nt = 0; nt < 2; nt++) {
                    int ch = ch0 + nt * 8 + 2 * tg;
                    float u0 = acc[mt][nt][hf * 2]     * IWSCALE;
                    float u1 = acc[mt][nt][hf * 2 + 1] * IWSCALE;
                    float q0 = acc[mt][nt + 2][hf * 2]     * IWSCALE;
                    float q1 = acc[mt][nt + 2][hf * 2 + 1] * IWSCALE;
                    float h0 = u0 * (q0 / (1.f + __expf(-q0)));
                    float h1 = u1 * (q1 / (1.f + __expf(-q1)));
                    *(__half2*)(orow + ch) = __floats2half2_rn(h0, h1);
                }
            }
        }
    }
}

// ---------------- kernel 5: down GEMM (fp16 mma, 128x256 block, K=2048) ----------------
#define KTD (HID / BK)    // 64

__global__ void __launch_bounds__(512) k_down() {
    extern __shared__ __half smem[];
    int tid = threadIdx.x, wid = tid >> 5, lane = tid & 31;
    int g = lane >> 2, tg = lane & 3;

    Sched sc = sched_rowtile(blockIdx.y);
    if (!sc.ok) return;
    int n0 = blockIdx.x * 256;

    int arow = tid >> 2, ac = tid & 3;
    const __half* a_src = g_h + (size_t)(sc.pbase + arow) * HID + ac * 8;  // pad rows cover overrun
    uint32_t a_dst = sptr(smem) + (arow * ASTRH + ac * 8) * 2;
    int br = tid >> 1;
    const __half* WD = g_wdn + (size_t)sc.e * DIMX * HID;
    const __half* b_src = WD + (size_t)(n0 + br) * HID + (tid & 1) * 16;
    uint32_t b_dst = sptr(smem) + (SB_OFF + br * ASTRH + (tid & 1) * 16) * 2;

    auto load_tile = [&](int ti) {
        uint32_t so = (uint32_t)(ti & (STAGES - 1)) * STG_B;
        cp16(a_dst + so, a_src + ti * BK);
        cp16(b_dst + so, b_src + ti * BK);
        cp16(b_dst + so + 16, b_src + ti * BK + 8);
    };

    load_tile(0); cp_commit();
    load_tile(1); cp_commit();
    load_tile(2); cp_commit();

    float acc[4][4][4] = {};
    int wm = (wid >> 3) * 64, wq = wid & 7;

    for (int kt = 0; kt < KTD; kt++) {
        if (kt + 3 < KTD) load_tile(kt + 3);
        cp_commit();
        asm volatile("cp.async.wait_group 3;");
        __syncthreads();
        const __half* S = smem + (kt & (STAGES - 1)) * STG_H;
        #pragma unroll
        for (int ks = 0; ks < 2; ks++) {
            int ko = ks * 16;
            uint32_t a[4][4];
            #pragma unroll
            for (int mt = 0; mt < 4; mt++) {
                int m0 = wm + mt * 16 + g;
                a[mt][0] = *(const uint32_t*)&S[m0 * ASTRH + ko + 2 * tg];
                a[mt][1] = *(const uint32_t*)&S[(m0 + 8) * ASTRH + ko + 2 * tg];
                a[mt][2] = *(const uint32_t*)&S[m0 * ASTRH + ko + 2 * tg + 8];
                a[mt][3] = *(const uint32_t*)&S[(m0 + 8) * ASTRH + ko + 2 * tg + 8];
            }
            #pragma unroll
            for (int nt = 0; nt < 4; nt++) {
                int nr = wq * 32 + nt * 8 + g;
                uint32_t b0 = *(const uint32_t*)&S[SB_OFF + nr * ASTRH + ko + 2 * tg];
                uint32_t b1 = *(const uint32_t*)&S[SB_OFF + nr * ASTRH + ko + 2 * tg + 8];
                #pragma unroll
                for (int mt = 0; mt < 4; mt++)
                    mma_f16(acc[mt][nt], a[mt], b0, b1);
            }
        }
        __syncthreads();
    }

    #pragma unroll
    for (int mt = 0; mt < 4; mt++) {
        #pragma unroll
        for (int hf = 0; hf < 2; hf++) {
            int r = wm + mt * 16 + g + hf * 8;
            if (r < sc.valid) {
                float* orow = g_down + (size_t)(sc.pbase + r) * DIMX + n0;
                #pragma unroll
                for (int nt = 0; nt < 4; nt++) {
                    int cc = wq * 32 + nt * 8 + 2 * tg;
                    float2 v;
                    v.x = acc[mt][nt][hf * 2]     * IWSCALE;
                    v.y = acc[mt][nt][hf * 2 + 1] * IWSCALE;
                    *(float2*)(orow + cc) = v;
                }
            }
        }
    }
}

// ---------------- kernel 6: combine out = x + w0*down[p0] + w1*down[p1] ----------------
__global__ void k_combine(const float* __restrict__ x, float* __restrict__ out) {
    int t = blockIdx.x, tid = threadIdx.x;
    int e0 = g_se[2 * t], j0 = g_sj[2 * t];
    int e1 = g_se[2 * t + 1], j1 = g_sj[2 * t + 1];
    float w0 = g_sw[2 * t], w1 = g_sw[2 * t + 1];
    int off0 = 0, off1 = 0;
    #pragma unroll
    for (int i = 0; i < 8; i++) {
        int ci = __ldg(&g_cnt[i]);
        if (i < e0) off0 += ci;
        if (i < e1) off1 += ci;
    }
    int p0 = off0 + j0, p1 = off1 + j1;
    const float4* x4 = (const float4*)(x + (size_t)t * DIMX);
    const float4* d0 = (const float4*)(g_down + (size_t)p0 * DIMX);
    const float4* d1 = (const float4*)(g_down + (size_t)p1 * DIMX);
    float4 a = x4[tid], u = d0[tid], v = d1[tid];
    float4 o;
    o.x = a.x + w0 * u.x + w1 * v.x;
    o.y = a.y + w0 * u.y + w1 * v.y;
    o.z = a.z + w0 * u.z + w1 * v.z;
    o.w = a.w + w0 * u.w + w1 * v.w;
    ((float4*)(out + (size_t)t * DIMX))[tid] = o;
}

// ---------------- launch ----------------
extern "C" void kernel_launch(void* const* d_in, const int* in_sizes, int n_in,
                              void* d_out, int out_size) {
    const float* x     = (const float*)d_in[0];
    const float* scale = (const float*)d_in[1];
    const float* wr    = (const float*)d_in[2];
    const float* wu    = (const float*)d_in[3];
    const float* wd    = (const float*)d_in[4];
    float* out = (float*)d_out;

    cudaFuncSetAttribute(k_up,   cudaFuncAttributeMaxDynamicSharedMemorySize, SMEM_TOT);
    cudaFuncSetAttribute(k_down, cudaFuncAttributeMaxDynamicSharedMemorySize, SMEM_TOT);

    k_zero<<<1, 32>>>();
    k_prep<<<2048, 256>>>(wu, wd);
    k_rms_router<<<M_TOK, 256>>>(x, scale, wr);
    // grid: x = n-tile (fast: a wave shares A row-tile, keeps B in L2), y = row-tile (264 >= 263 worst case)
    k_up  <<<dim3(HID / 128, 264), 512, SMEM_TOT>>>();   // (16, 264)
    k_down<<<dim3(DIMX / 256, 264), 512, SMEM_TOT>>>();  // (4, 264)
    k_combine<<<M_TOK, 256>>>(x, out);
}

// round 10
// speedup vs baseline: 2.3535x; 1.2149x over previous
#include <cuda_runtime.h>
#include <cuda_fp16.h>
#include <math.h>
#include <cstdint>

// ---------------- problem constants ----------------
#define M_TOK   16384            // 4 * 4096 tokens
#define DIMX    1024
#define HID     2048
#define NEXP    8
#define TOPK    2
#define RROWS   (M_TOK * TOPK)   // 32768 (token, slot) rows

#define WSCALE   1024.0f         // weight pre-scale (exact power of 2)
#define IWSCALE  (1.0f / 1024.0f)

// ---------------- device scratch (static .bss; no allocations) ----------------
__device__ __half g_xn[(size_t)M_TOK * DIMX];             // fp16 normalized activations
__device__ __half g_h[(size_t)(RROWS + 128) * HID];       // fp16 SwiGLU output, +pad rows
__device__ float  g_down[(size_t)RROWS * DIMX];           // down-proj per (token,slot), unweighted
__device__ __half g_wup[(size_t)NEXP * 2 * HID * DIMX];   // fp16 w_up * 1024
__device__ __half g_wdn[(size_t)NEXP * DIMX * HID];       // fp16 w_down * 1024
__device__ int    g_cnt[NEXP];
__device__ int    g_list[NEXP * M_TOK];                   // per-expert token lists
__device__ int    g_se[RROWS];
__device__ int    g_sj[RROWS];
__device__ float  g_sw[RROWS];

// ---------------- helpers ----------------
__device__ __forceinline__ unsigned sptr(const void* p) {
    return (unsigned)__cvta_generic_to_shared(p);
}
__device__ __forceinline__ void cp16(unsigned s, const void* g) {
    asm volatile("cp.async.cg.shared.global [%0], [%1], 16;" :: "r"(s), "l"(g));
}
__device__ __forceinline__ void cp_commit() { asm volatile("cp.async.commit_group;"); }

// fp16 MMA, f32 accumulate: D(16x8) += A(16x16) * B(16x8)
__device__ __forceinline__ void mma_f16(float* c, const uint32_t* a, uint32_t b0, uint32_t b1) {
    asm volatile(
        "mma.sync.aligned.m16n8k16.row.col.f32.f16.f16.f32 "
        "{%0,%1,%2,%3}, {%4,%5,%6,%7}, {%8,%9}, {%0,%1,%2,%3};"
        : "+f"(c[0]), "+f"(c[1]), "+f"(c[2]), "+f"(c[3])
        : "r"(a[0]), "r"(a[1]), "r"(a[2]), "r"(a[3]), "r"(b0), "r"(b1));
}
__device__ __forceinline__ void ldsm_x4(uint32_t* r, uint32_t addr) {
    asm volatile("ldmatrix.sync.aligned.m8n8.x4.shared.b16 {%0,%1,%2,%3}, [%4];"
        : "=r"(r[0]), "=r"(r[1]), "=r"(r[2]), "=r"(r[3]) : "r"(addr));
}
__device__ __forceinline__ void ldsm_x2(uint32_t& r0, uint32_t& r1, uint32_t addr) {
    asm volatile("ldmatrix.sync.aligned.m8n8.x2.shared.b16 {%0,%1}, [%2];"
        : "=r"(r0), "=r"(r1) : "r"(addr));
}

// ---------------- GEMM geometry ----------------
// block tile 128(M) x 128(N), BK=32, 256 threads = 8 warps as 2(M) x 4(N), warp tile 64x32
// 3 stages, 62KB smem -> 2 CTAs/SM (two independent barrier domains per SM)
#define BK      32
#define BM      128
#define BN      128
#define ASTRH   40                        // smem halves per 32-half row (80B, padded): LDSM phases conflict-free
#define STG_H   ((BM + BN) * ASTRH)       // 10240 halves per stage
#define STG_B   (STG_H * 2)               // 20480 bytes
#define STAGES  3
#define TOKS_H  (STAGES * STG_H)          // toks array after stages (half index)
#define SMEM_TOT (TOKS_H * 2 + 512)       // 61952 bytes

// ---------------- kernel 1: zero counters ----------------
__global__ void k_zero() {
    if (threadIdx.x < NEXP) g_cnt[threadIdx.x] = 0;
}

// ---------------- kernel 2: convert weights to fp16 * 1024 ----------------
__global__ void k_prep(const float* __restrict__ wu, const float* __restrict__ wd) {
    int i = blockIdx.x * blockDim.x + threadIdx.x;
    int stride = gridDim.x * blockDim.x;
    const int NU = NEXP * 2 * HID * DIMX / 4;
    const int ND = NEXP * DIMX * HID / 4;
    const float4* u4 = (const float4*)wu;
    const float4* d4 = (const float4*)wd;
    for (int j = i; j < NU; j += stride) {
        float4 v = u4[j];
        __half2* o = (__half2*)(g_wup + (size_t)j * 4);
        o[0] = __floats2half2_rn(v.x * WSCALE, v.y * WSCALE);
        o[1] = __floats2half2_rn(v.z * WSCALE, v.w * WSCALE);
    }
    for (int j = i; j < ND; j += stride) {
        float4 v = d4[j];
        __half2* o = (__half2*)(g_wdn + (size_t)j * 4);
        o[0] = __floats2half2_rn(v.x * WSCALE, v.y * WSCALE);
        o[1] = __floats2half2_rn(v.z * WSCALE, v.w * WSCALE);
    }
}

// ---------------- kernel 3: RMSNorm + router + top2 + softmax + list build ----------------
__global__ void k_rms_router(const float* __restrict__ x,
                             const float* __restrict__ scale,
                             const float* __restrict__ wr) {
    __shared__ float sx[DIMX];
    __shared__ float sred[8];
    __shared__ float sscore[8];
    int t = blockIdx.x, tid = threadIdx.x;

    const float4* xr = (const float4*)(x + (size_t)t * DIMX);
    float4 v = xr[tid];
    float ss = v.x * v.x + v.y * v.y + v.z * v.z + v.w * v.w;
    #pragma unroll
    for (int o = 16; o; o >>= 1) ss += __shfl_xor_sync(0xffffffffu, ss, o);
    if ((tid & 31) == 0) sred[tid >> 5] = ss;
    __syncthreads();
    if (tid == 0) {
        float a = 0.f;
        #pragma unroll
        for (int i = 0; i < 8; i++) a += sred[i];
        sred[0] = a;
    }
    __syncthreads();
    float ms = sred[0] * (1.0f / (float)DIMX);
    float rs = rsqrtf(ms + 1e-6f);
    float4 sc = ((const float4*)scale)[tid];
    float4 xn;
    xn.x = v.x * sc.x * rs; xn.y = v.y * sc.y * rs;
    xn.z = v.z * sc.z * rs; xn.w = v.w * sc.w * rs;
    ((float4*)sx)[tid] = xn;                       // full precision for router
    __half2* hp = (__half2*)(g_xn + (size_t)t * DIMX + 4 * tid);
    hp[0] = __floats2half2_rn(xn.x, xn.y);
    hp[1] = __floats2half2_rn(xn.z, xn.w);
    __syncthreads();

    int w = tid >> 5, lane = tid & 31;
    const float* wrow = wr + w * DIMX;
    float acc = 0.f;
    #pragma unroll 8
    for (int j = lane; j < DIMX; j += 32) acc += sx[j] * __ldg(wrow + j);
    #pragma unroll
    for (int o = 16; o; o >>= 1) acc += __shfl_xor_sync(0xffffffffu, acc, o);
    if (lane == 0) sscore[w] = acc;
    __syncthreads();

    if (tid == 0) {
        float s0 = -1e30f; int i0 = 0;
        #pragma unroll
        for (int i = 0; i < 8; i++) { float s = sscore[i]; if (s > s0) { s0 = s; i0 = i; } }
        float s1 = -1e30f; int i1 = 0;
        #pragma unroll
        for (int i = 0; i < 8; i++) { if (i == i0) continue; float s = sscore[i]; if (s > s1) { s1 = s; i1 = i; } }
        float e1 = __expf(s1 - s0);
        float w0 = 1.f / (1.f + e1);
        float w1 = e1 * w0;
        int p0 = atomicAdd(&g_cnt[i0], 1);
        g_list[i0 * M_TOK + p0] = t;
        g_se[2 * t] = i0; g_sj[2 * t] = p0; g_sw[2 * t] = w0;
        int p1 = atomicAdd(&g_cnt[i1], 1);
        g_list[i1 * M_TOK + p1] = t;
        g_se[2 * t + 1] = i1; g_sj[2 * t + 1] = p1; g_sw[2 * t + 1] = w1;
    }
}

// ---------------- scheduling: blockIdx.y -> (expert, row-tile) ----------------
struct Sched { int e, rt, valid, pbase; bool ok; };
__device__ __forceinline__ Sched sched_rowtile(int tile) {
    Sched s; s.ok = false;
    int off = 0;
    for (int e = 0; e < NEXP; e++) {
        int c = g_cnt[e];
        int nt = (c + 127) >> 7;
        if (tile < nt) {
            s.e = e; s.rt = tile;
            s.valid = min(128, c - tile * 128);
            s.pbase = off + tile * 128;
            s.ok = true;
            return s;
        }
        tile -= nt; off += c;
    }
    return s;
}

// ---------------- kernel 4: up GEMM (fp16 mma; block covers 64 u + 64 gate cols) ----------------
#define KTU (DIMX / BK)   // 32

__global__ void __launch_bounds__(256, 2) k_up() {
    extern __shared__ __half smem[];
    int tid = threadIdx.x, wid = tid >> 5, lane = tid & 31;
    int g = lane >> 2, tg = lane & 3;

    Sched sc = sched_rowtile(blockIdx.y);
    if (!sc.ok) return;
    int c0 = blockIdx.x * 64;           // u/gate HID column base
    int lbase = sc.e * M_TOK + sc.rt * 128;

    int* toks = (int*)(smem + TOKS_H);
    if (tid < 128)
        toks[tid] = (tid < sc.valid) ? g_list[lbase + tid] : g_list[lbase];
    __syncthreads();

    // A loader: thread t -> row t>>1, 16-half group t&1 (two cp16)
    int arow = tid >> 1;
    const __half* a_src = g_xn + (size_t)toks[arow] * DIMX + (tid & 1) * 16;
    uint32_t a_dst = sptr(smem) + (arow * ASTRH + (tid & 1) * 16) * 2;
    // B loader: block row br = w8*32 + j: j<16 -> u col c0+w8*16+j ; j>=16 -> gate
    int br = tid >> 1, w8 = br >> 5, j = br & 31;
    int bhid = c0 + w8 * 16 + (j & 15);
    int brow = (j < 16) ? bhid : (HID + bhid);
    const __half* WU = g_wup + (size_t)sc.e * 2 * HID * DIMX;
    const __half* b_src = WU + (size_t)brow * DIMX + (tid & 1) * 16;
    uint32_t b_dst = sptr(smem) + ((BM + br) * ASTRH + (tid & 1) * 16) * 2;

    auto load_tile = [&](int ti, int st) {
        uint32_t so = (uint32_t)st * STG_B;
        const __half* ap = a_src + ti * BK;
        const __half* bp = b_src + ti * BK;
        cp16(a_dst + so, ap);
        cp16(a_dst + so + 16, ap + 8);
        cp16(b_dst + so, bp);
        cp16(b_dst + so + 16, bp + 8);
    };

    load_tile(0, 0); cp_commit();
    load_tile(1, 1); cp_commit();

    float acc[4][4][4] = {};
    int wm = (wid >> 2) * 64, wq = wid & 3;
    // LDSM per-thread offsets (bytes within stage)
    uint32_t sbase = sptr(smem);
    uint32_t a_off = ((wm + (lane & 15)) * ASTRH + (lane >> 4) * 8) * 2;
    uint32_t b_off = ((BM + wq * 32 + (lane & 7)) * ASTRH + ((lane >> 3) & 1) * 8) * 2;

    int st_r = 0, st_w = 2;
    for (int kt = 0; kt < KTU; kt++) {
        asm volatile("cp.async.wait_group 1;");
        __syncthreads();
        uint32_t Sb = sbase + (uint32_t)st_r * STG_B;
        #pragma unroll
        for (int ks = 0; ks < 2; ks++) {
            uint32_t a[4][4];
            #pragma unroll
            for (int mt = 0; mt < 4; mt++)
                ldsm_x4(a[mt], Sb + a_off + mt * (16 * ASTRH * 2) + ks * 32);
            #pragma unroll
            for (int nt = 0; nt < 4; nt++) {
                uint32_t b0, b1;
                ldsm_x2(b0, b1, Sb + b_off + nt * (8 * ASTRH * 2) + ks * 32);
                #pragma unroll
                for (int mt = 0; mt < 4; mt++)
                    mma_f16(acc[mt][nt], a[mt], b0, b1);
            }
        }
        if (kt + 2 < KTU) load_tile(kt + 2, st_w);
        cp_commit();
        if (++st_r == STAGES) st_r = 0;
        if (++st_w == STAGES) st_w = 0;
    }

    // SwiGLU: warp covers HID cols [c0+wq*16, +16); nt 0..1 = u, nt 2..3 = gate (same cols)
    int ch0 = c0 + wq * 16;
    #pragma unroll
    for (int mt = 0; mt < 4; mt++) {
        #pragma unroll
        for (int hf = 0; hf < 2; hf++) {
            int r = wm + mt * 16 + g + hf * 8;
            if (r < sc.valid) {
                __half* orow = g_h + (size_t)(sc.pbase + r) * HID;
                #pragma unroll
                for (int nt = 0; nt < 2; nt++) {
                    int ch = ch0 + nt * 8 + 2 * tg;
                    float u0 = acc[mt][nt][hf * 2]     * IWSCALE;
                    float u1 = acc[mt][nt][hf * 2 + 1] * IWSCALE;
                    float q0 = acc[mt][nt + 2][hf * 2]     * IWSCALE;
                    float q1 = acc[mt][nt + 2][hf * 2 + 1] * IWSCALE;
                    float h0 = u0 * (q0 / (1.f + __expf(-q0)));
                    float h1 = u1 * (q1 / (1.f + __expf(-q1)));
                    *(__half2*)(orow + ch) = __floats2half2_rn(h0, h1);
                }
            }
        }
    }
}

// ---------------- kernel 5: down GEMM (fp16 mma, 128x128 block, K=2048) ----------------
#define KTD (HID / BK)    // 64

__global__ void __launch_bounds__(256, 2) k_down() {
    extern __shared__ __half smem[];
    int tid = threadIdx.x, wid = tid >> 5, lane = tid & 31;
    int g = lane >> 2, tg = lane & 3;

    Sched sc = sched_rowtile(blockIdx.y);
    if (!sc.ok) return;
    int n0 = blockIdx.x * BN;

    int arow = tid >> 1;
    const __half* a_src = g_h + (size_t)(sc.pbase + arow) * HID + (tid & 1) * 16;  // pad rows cover overrun
    uint32_t a_dst = sptr(smem) + (arow * ASTRH + (tid & 1) * 16) * 2;
    const __half* WD = g_wdn + (size_t)sc.e * DIMX * HID;
    const __half* b_src = WD + (size_t)(n0 + arow) * HID + (tid & 1) * 16;
    uint32_t b_dst = sptr(smem) + ((BM + arow) * ASTRH + (tid & 1) * 16) * 2;

    auto load_tile = [&](int ti, int st) {
        uint32_t so = (uint32_t)st * STG_B;
        const __half* ap = a_src + ti * BK;
        const __half* bp = b_src + ti * BK;
        cp16(a_dst + so, ap);
        cp16(a_dst + so + 16, ap + 8);
        cp16(b_dst + so, bp);
        cp16(b_dst + so + 16, bp + 8);
    };

    load_tile(0, 0); cp_commit();
    load_tile(1, 1); cp_commit();

    float acc[4][4][4] = {};
    int wm = (wid >> 2) * 64, wq = wid & 3;
    uint32_t sbase = sptr(smem);
    uint32_t a_off = ((wm + (lane & 15)) * ASTRH + (lane >> 4) * 8) * 2;
    uint32_t b_off = ((BM + wq * 32 + (lane & 7)) * ASTRH + ((lane >> 3) & 1) * 8) * 2;

    int st_r = 0, st_w = 2;
    for (int kt = 0; kt < KTD; kt++) {
        asm volatile("cp.async.wait_group 1;");
        __syncthreads();
        uint32_t Sb = sbase + (uint32_t)st_r * STG_B;
        #pragma unroll
        for (int ks = 0; ks < 2; ks++) {
            uint32_t a[4][4];
            #pragma unroll
            for (int mt = 0; mt < 4; mt++)
                ldsm_x4(a[mt], Sb + a_off + mt * (16 * ASTRH * 2) + ks * 32);
            #pragma unroll
            for (int nt = 0; nt < 4; nt++) {
                uint32_t b0, b1;
                ldsm_x2(b0, b1, Sb + b_off + nt * (8 * ASTRH * 2) + ks * 32);
                #pragma unroll
                for (int mt = 0; mt < 4; mt++)
                    mma_f16(acc[mt][nt], a[mt], b0, b1);
            }
        }
        if (kt + 2 < KTD) load_tile(kt + 2, st_w);
        cp_commit();
        if (++st_r == STAGES) st_r = 0;
        if (++st_w == STAGES) st_w = 0;
    }

    #pragma unroll
    for (int mt = 0; mt < 4; mt++) {
        #pragma unroll
        for (int hf = 0; hf < 2; hf++) {
            int r = wm + mt * 16 + g + hf * 8;
            if (r < sc.valid) {
                float* orow = g_down + (size_t)(sc.pbase + r) * DIMX + n0;
                #pragma unroll
                for (int nt = 0; nt < 4; nt++) {
                    int cc = wq * 32 + nt * 8 + 2 * tg;
                    float2 v;
                    v.x = acc[mt][nt][hf * 2]     * IWSCALE;
                    v.y = acc[mt][nt][hf * 2 + 1] * IWSCALE;
                    *(float2*)(orow + cc) = v;
                }
            }
        }
    }
}

// ---------------- kernel 6: combine out = x + w0*down[p0] + w1*down[p1] ----------------
__global__ void k_combine(const float* __restrict__ x, float* __restrict__ out) {
    int t = blockIdx.x, tid = threadIdx.x;
    int e0 = g_se[2 * t], j0 = g_sj[2 * t];
    int e1 = g_se[2 * t + 1], j1 = g_sj[2 * t + 1];
    float w0 = g_sw[2 * t], w1 = g_sw[2 * t + 1];
    int off0 = 0, off1 = 0;
    #pragma unroll
    for (int i = 0; i < 8; i++) {
        int ci = __ldg(&g_cnt[i]);
        if (i < e0) off0 += ci;
        if (i < e1) off1 += ci;
    }
    int p0 = off0 + j0, p1 = off1 + j1;
    const float4* x4 = (const float4*)(x + (size_t)t * DIMX);
    const float4* d0 = (const float4*)(g_down + (size_t)p0 * DIMX);
    const float4* d1 = (const float4*)(g_down + (size_t)p1 * DIMX);
    float4 a = x4[tid], u = d0[tid], v = d1[tid];
    float4 o;
    o.x = a.x + w0 * u.x + w1 * v.x;
    o.y = a.y + w0 * u.y + w1 * v.y;
    o.z = a.z + w0 * u.z + w1 * v.z;
    o.w = a.w + w0 * u.w + w1 * v.w;
    ((float4*)(out + (size_t)t * DIMX))[tid] = o;
}

// ---------------- launch ----------------
extern "C" void kernel_launch(void* const* d_in, const int* in_sizes, int n_in,
                              void* d_out, int out_size) {
    const float* x     = (const float*)d_in[0];
    const float* scale = (const float*)d_in[1];
    const float* wr    = (const float*)d_in[2];
    const float* wu    = (const float*)d_in[3];
    const float* wd    = (const float*)d_in[4];
    float* out = (float*)d_out;

    cudaFuncSetAttribute(k_up,   cudaFuncAttributeMaxDynamicSharedMemorySize, SMEM_TOT);
    cudaFuncSetAttribute(k_down, cudaFuncAttributeMaxDynamicSharedMemorySize, SMEM_TOT);

    k_zero<<<1, 32>>>();
    k_prep<<<2048, 256>>>(wu, wd);
    k_rms_router<<<M_TOK, 256>>>(x, scale, wr);
    // grid: x = n-tile (fast: a wave shares A row-tile, keeps B in L2), y = row-tile (264 >= 263 worst case)
    k_up  <<<dim3(HID / 64, 264), 256, SMEM_TOT>>>();    // (32, 264)
    k_down<<<dim3(DIMX / BN, 264), 256, SMEM_TOT>>>();   // (8, 264)
    k_combine<<<M_TOK, 256>>>(x, out);
}

// round 13
// speedup vs baseline: 2.7609x; 1.1731x over previous
#include <cuda_runtime.h>
#include <cuda_fp16.h>
#include <math.h>
#include <cstdint>

// ---------------- problem constants ----------------
#define M_TOK   16384            // 4 * 4096 tokens
#define DIMX    1024
#define HID     2048
#define NEXP    8
#define TOPK    2
#define RROWS   (M_TOK * TOPK)   // 32768 (token, slot) rows

#define WSCALE   1024.0f         // weight pre-scale (exact power of 2)
#define IWSCALE  (1.0f / 1024.0f)

// ---------------- device scratch (static .bss; no allocations) ----------------
__device__ __half g_xn[(size_t)M_TOK * DIMX];             // fp16 normalized activations
__device__ __half g_h[(size_t)(RROWS + 128) * HID];       // fp16 SwiGLU output, +pad rows
__device__ float  g_down[(size_t)RROWS * DIMX];           // down-proj per (token,slot), unweighted
__device__ __half g_wup[(size_t)NEXP * 2 * HID * DIMX];   // fp16 w_up * 1024
__device__ __half g_wdn[(size_t)NEXP * DIMX * HID];       // fp16 w_down * 1024
__device__ int    g_cnt[NEXP];
__device__ int    g_list[NEXP * M_TOK];                   // per-expert token lists
__device__ int    g_se[RROWS];
__device__ int    g_sj[RROWS];
__device__ float  g_sw[RROWS];

// ---------------- helpers ----------------
__device__ __forceinline__ unsigned sptr(const void* p) {
    return (unsigned)__cvta_generic_to_shared(p);
}
__device__ __forceinline__ void cp16(unsigned s, const void* g) {
    asm volatile("cp.async.cg.shared.global [%0], [%1], 16;" :: "r"(s), "l"(g));
}
// arrive on mbarrier when ALL prior cp.async of this thread have completed.
// .noinc is LOAD-BEARING: the barrier's init count already includes this arrival;
// without .noinc the pending count is incremented at issue (net zero) and the
// barrier never flips -> deadlock (round-12 timeout).
__device__ __forceinline__ void cp_arrive(uint32_t mbar) {
    asm volatile("cp.async.mbarrier.arrive.noinc.shared::cta.b64 [%0];" :: "r"(mbar) : "memory");
}
__device__ __forceinline__ void mbar_init(uint32_t a, uint32_t cnt) {
    asm volatile("mbarrier.init.shared.b64 [%0], %1;" :: "r"(a), "r"(cnt) : "memory");
}
__device__ __forceinline__ void mbar_arrive(uint32_t a) {
    asm volatile("mbarrier.arrive.shared.b64 _, [%0];" :: "r"(a) : "memory");
}
__device__ __forceinline__ void mbar_wait(uint32_t a, uint32_t par) {
    uint32_t done;
    asm volatile(
        "{\n\t.reg .pred p;\n\t"
        "mbarrier.try_wait.parity.acquire.cta.shared::cta.b64 p, [%1], %2;\n\t"
        "selp.b32 %0, 1, 0, p;\n\t}"
        : "=r"(done) : "r"(a), "r"(par) : "memory");
    if (!done) {
        asm volatile(
            "{\n\t.reg .pred P1;\n\t"
            "WL%=:\n\t"
            "mbarrier.try_wait.parity.acquire.cta.shared::cta.b64 P1, [%0], %1, 0x989680;\n\t"
            "@P1 bra.uni WD%=;\n\t"
            "bra.uni WL%=;\n\t"
            "WD%=:\n\t}"
            :: "r"(a), "r"(par) : "memory");
    }
}

// fp16 MMA, f32 accumulate: D(16x8) += A(16x16) * B(16x8)
__device__ __forceinline__ void mma_f16(float* c, const uint32_t* a, uint32_t b0, uint32_t b1) {
    asm volatile(
        "mma.sync.aligned.m16n8k16.row.col.f32.f16.f16.f32 "
        "{%0,%1,%2,%3}, {%4,%5,%6,%7}, {%8,%9}, {%0,%1,%2,%3};"
        : "+f"(c[0]), "+f"(c[1]), "+f"(c[2]), "+f"(c[3])
        : "r"(a[0]), "r"(a[1]), "r"(a[2]), "r"(a[3]), "r"(b0), "r"(b1));
}
__device__ __forceinline__ void ldsm_x4(uint32_t* r, uint32_t addr) {
    asm volatile("ldmatrix.sync.aligned.m8n8.x4.shared.b16 {%0,%1,%2,%3}, [%4];"
        : "=r"(r[0]), "=r"(r[1]), "=r"(r[2]), "=r"(r[3]) : "r"(addr));
}
__device__ __forceinline__ void ldsm_x2(uint32_t& r0, uint32_t& r1, uint32_t addr) {
    asm volatile("ldmatrix.sync.aligned.m8n8.x2.shared.b16 {%0,%1}, [%2];"
        : "=r"(r0), "=r"(r1) : "r"(addr));
}

// ---------------- GEMM geometry ----------------
// block tile 128(M) x 128(N), BK=32, 256 threads = 8 warps as 2(M) x 4(N), warp tile 64x32
// 4 stages + mbarrier producer/consumer pipeline (no __syncthreads in mainloop)
// 82KB smem, ~122 regs -> 2 CTAs/SM (two independent pipeline domains per SM)
#define BK      32
#define BM      128
#define BN      128
#define ASTRH   40                        // smem halves per 32-half row (80B, padded): LDSM phases conflict-free
#define STG_H   ((BM + BN) * ASTRH)       // 10240 halves per stage
#define STG_B   (STG_H * 2)               // 20480 bytes
#define STAGES  4
#define BAR_OFF (STAGES * STG_B)          // byte offset of mbarriers: 81920
#define TOKS_OFF (BAR_OFF + 64)           // byte offset of toks
#define SMEM_TOT (TOKS_OFF + 512)         // 82496 bytes

// ---------------- kernel 1: zero counters ----------------
__global__ void k_zero() {
    if (threadIdx.x < NEXP) g_cnt[threadIdx.x] = 0;
}

// ---------------- kernel 2: convert weights to fp16 * 1024 ----------------
__global__ void k_prep(const float* __restrict__ wu, const float* __restrict__ wd) {
    int i = blockIdx.x * blockDim.x + threadIdx.x;
    int stride = gridDim.x * blockDim.x;
    const int NU = NEXP * 2 * HID * DIMX / 4;
    const int ND = NEXP * DIMX * HID / 4;
    const float4* u4 = (const float4*)wu;
    const float4* d4 = (const float4*)wd;
    for (int j = i; j < NU; j += stride) {
        float4 v = u4[j];
        __half2* o = (__half2*)(g_wup + (size_t)j * 4);
        o[0] = __floats2half2_rn(v.x * WSCALE, v.y * WSCALE);
        o[1] = __floats2half2_rn(v.z * WSCALE, v.w * WSCALE);
    }
    for (int j = i; j < ND; j += stride) {
        float4 v = d4[j];
        __half2* o = (__half2*)(g_wdn + (size_t)j * 4);
        o[0] = __floats2half2_rn(v.x * WSCALE, v.y * WSCALE);
        o[1] = __floats2half2_rn(v.z * WSCALE, v.w * WSCALE);
    }
}

// ---------------- kernel 3: RMSNorm + router + top2 + softmax + list build ----------------
__global__ void k_rms_router(const float* __restrict__ x,
                             const float* __restrict__ scale,
                             const float* __restrict__ wr) {
    __shared__ float sx[DIMX];
    __shared__ float sred[8];
    __shared__ float sscore[8];
    int t = blockIdx.x, tid = threadIdx.x;

    const float4* xr = (const float4*)(x + (size_t)t * DIMX);
    float4 v = xr[tid];
    float ss = v.x * v.x + v.y * v.y + v.z * v.z + v.w * v.w;
    #pragma unroll
    for (int o = 16; o; o >>= 1) ss += __shfl_xor_sync(0xffffffffu, ss, o);
    if ((tid & 31) == 0) sred[tid >> 5] = ss;
    __syncthreads();
    if (tid == 0) {
        float a = 0.f;
        #pragma unroll
        for (int i = 0; i < 8; i++) a += sred[i];
        sred[0] = a;
    }
    __syncthreads();
    float ms = sred[0] * (1.0f / (float)DIMX);
    float rs = rsqrtf(ms + 1e-6f);
    float4 sc = ((const float4*)scale)[tid];
    float4 xn;
    xn.x = v.x * sc.x * rs; xn.y = v.y * sc.y * rs;
    xn.z = v.z * sc.z * rs; xn.w = v.w * sc.w * rs;
    ((float4*)sx)[tid] = xn;                       // full precision for router
    __half2* hp = (__half2*)(g_xn + (size_t)t * DIMX + 4 * tid);
    hp[0] = __floats2half2_rn(xn.x, xn.y);
    hp[1] = __floats2half2_rn(xn.z, xn.w);
    __syncthreads();

    int w = tid >> 5, lane = tid & 31;
    const float* wrow = wr + w * DIMX;
    float acc = 0.f;
    #pragma unroll 8
    for (int j = lane; j < DIMX; j += 32) acc += sx[j] * __ldg(wrow + j);
    #pragma unroll
    for (int o = 16; o; o >>= 1) acc += __shfl_xor_sync(0xffffffffu, acc, o);
    if (lane == 0) sscore[w] = acc;
    __syncthreads();

    if (tid == 0) {
        float s0 = -1e30f; int i0 = 0;
        #pragma unroll
        for (int i = 0; i < 8; i++) { float s = sscore[i]; if (s > s0) { s0 = s; i0 = i; } }
        float s1 = -1e30f; int i1 = 0;
        #pragma unroll
        for (int i = 0; i < 8; i++) { if (i == i0) continue; float s = sscore[i]; if (s > s1) { s1 = s; i1 = i; } }
        float e1 = __expf(s1 - s0);
        float w0 = 1.f / (1.f + e1);
        float w1 = e1 * w0;
        int p0 = atomicAdd(&g_cnt[i0], 1);
        g_list[i0 * M_TOK + p0] = t;
        g_se[2 * t] = i0; g_sj[2 * t] = p0; g_sw[2 * t] = w0;
        int p1 = atomicAdd(&g_cnt[i1], 1);
        g_list[i1 * M_TOK + p1] = t;
        g_se[2 * t + 1] = i1; g_sj[2 * t + 1] = p1; g_sw[2 * t + 1] = w1;
    }
}

// ---------------- scheduling: blockIdx.y -> (expert, row-tile) ----------------
struct Sched { int e, rt, valid, pbase; bool ok; };
__device__ __forceinline__ Sched sched_rowtile(int tile) {
    Sched s; s.ok = false;
    int off = 0;
    for (int e = 0; e < NEXP; e++) {
        int c = g_cnt[e];
        int nt = (c + 127) >> 7;
        if (tile < nt) {
            s.e = e; s.rt = tile;
            s.valid = min(128, c - tile * 128);
            s.pbase = off + tile * 128;
            s.ok = true;
            return s;
        }
        tile -= nt; off += c;
    }
    return s;
}

// ---------------- kernel 4: up GEMM (fp16 mma; block covers 64 u + 64 gate cols) ----------------
#define KTU (DIMX / BK)   // 32

__global__ void __launch_bounds__(256, 2) k_up() {
    extern __shared__ __half smem[];
    uint32_t sb = sptr(smem);
    int tid = threadIdx.x, wid = tid >> 5, lane = tid & 31;
    int g = lane >> 2, tg = lane & 3;

    Sched sc = sched_rowtile(blockIdx.y);
    if (!sc.ok) return;
    int c0 = blockIdx.x * 64;           // u/gate HID column base
    int lbase = sc.e * M_TOK + sc.rt * 128;

    uint32_t fullb = sb + BAR_OFF;       // 4 x 8B
    uint32_t emptyb = sb + BAR_OFF + 32; // 4 x 8B
    if (tid == 0) {
        #pragma unroll
        for (int s = 0; s < STAGES; s++) {
            mbar_init(fullb + 8 * s, 256);
            mbar_init(emptyb + 8 * s, 8);
        }
    }
    int* toks = (int*)((char*)smem + TOKS_OFF);
    if (tid < 128)
        toks[tid] = (tid < sc.valid) ? g_list[lbase + tid] : g_list[lbase];
    __syncthreads();

    // A loader: thread t -> row t>>1, 16-half group t&1 (two cp16)
    int arow = tid >> 1;
    const __half* a_src = g_xn + (size_t)toks[arow] * DIMX + (tid & 1) * 16;
    uint32_t a_dst = sb + (arow * ASTRH + (tid & 1) * 16) * 2;
    // B loader: block row br = w8*32 + j: j<16 -> u col c0+w8*16+j ; j>=16 -> gate
    int br = tid >> 1, w8 = br >> 5, j = br & 31;
    int bhid = c0 + w8 * 16 + (j & 15);
    int brow = (j < 16) ? bhid : (HID + bhid);
    const __half* WU = g_wup + (size_t)sc.e * 2 * HID * DIMX;
    const __half* b_src = WU + (size_t)brow * DIMX + (tid & 1) * 16;
    uint32_t b_dst = sb + ((BM + br) * ASTRH + (tid & 1) * 16) * 2;

    auto load_tile = [&](int ti, int st) {
        uint32_t so = (uint32_t)st * STG_B;
        const __half* ap = a_src + ti * BK;
        const __half* bp = b_src + ti * BK;
        cp16(a_dst + so, ap);
        cp16(a_dst + so + 16, ap + 8);
        cp16(b_dst + so, bp);
        cp16(b_dst + so + 16, bp + 8);
    };

    // prologue: produce tiles 0..2 (stages 0..2)
    #pragma unroll
    for (int ti = 0; ti < 3; ti++) {
        load_tile(ti, ti);
        cp_arrive(fullb + 8 * ti);
    }

    float acc[4][4][4] = {};
    int wm = (wid >> 2) * 64, wq = wid & 3;
    uint32_t a_off = ((wm + (lane & 15)) * ASTRH + (lane >> 4) * 8) * 2;
    uint32_t b_off = ((BM + wq * 32 + (lane & 7)) * ASTRH + ((lane >> 3) & 1) * 8) * 2;

    for (int kt = 0; kt < KTU; kt++) {
        int s = kt & 3;
        mbar_wait(fullb + 8 * s, (kt >> 2) & 1);
        uint32_t Sb = sb + (uint32_t)s * STG_B;
        #pragma unroll
        for (int ks = 0; ks < 2; ks++) {
            uint32_t a[4][4];
            #pragma unroll
            for (int mt = 0; mt < 4; mt++)
                ldsm_x4(a[mt], Sb + a_off + mt * (16 * ASTRH * 2) + ks * 32);
            #pragma unroll
            for (int nt = 0; nt < 4; nt++) {
                uint32_t b0, b1;
                ldsm_x2(b0, b1, Sb + b_off + nt * (8 * ASTRH * 2) + ks * 32);
                #pragma unroll
                for (int mt = 0; mt < 4; mt++)
                    mma_f16(acc[mt][nt], a[mt], b0, b1);
            }
        }
        if (lane == 0) mbar_arrive(emptyb + 8 * s);
        int ti = kt + 3;
        if (ti < KTU) {
            int s2 = ti & 3;
            if (ti >= 4) mbar_wait(emptyb + 8 * s2, ((ti >> 2) - 1) & 1);
            load_tile(ti, s2);
            cp_arrive(fullb + 8 * s2);
        }
    }

    // SwiGLU: warp covers HID cols [c0+wq*16, +16); nt 0..1 = u, nt 2..3 = gate (same cols)
    int ch0 = c0 + wq * 16;
    #pragma unroll
    for (int mt = 0; mt < 4; mt++) {
        #pragma unroll
        for (int hf = 0; hf < 2; hf++) {
            int r = wm + mt * 16 + g + hf * 8;
            if (r < sc.valid) {
                __half* orow = g_h + (size_t)(sc.pbase + r) * HID;
                #pragma unroll
                for (int nt = 0; nt < 2; nt++) {
                    int ch = ch0 + nt * 8 + 2 * tg;
                    float u0 = acc[mt][nt][hf * 2]     * IWSCALE;
                    float u1 = acc[mt][nt][hf * 2 + 1] * IWSCALE;
                    float q0 = acc[mt][nt + 2][hf * 2]     * IWSCALE;
                    float q1 = acc[mt][nt + 2][hf * 2 + 1] * IWSCALE;
                    float h0 = u0 * (q0 / (1.f + __expf(-q0)));
                    float h1 = u1 * (q1 / (1.f + __expf(-q1)));
                    *(__half2*)(orow + ch) = __floats2half2_rn(h0, h1);
                }
            }
        }
    }
}

// ---------------- kernel 5: down GEMM (fp16 mma, 128x128 block, K=2048) ----------------
#define KTD (HID / BK)    // 64

__global__ void __launch_bounds__(256, 2) k_down() {
    extern __shared__ __half smem[];
    uint32_t sb = sptr(smem);
    int tid = threadIdx.x, wid = tid >> 5, lane = tid & 31;
    int g = lane >> 2, tg = lane & 3;

    Sched sc = sched_rowtile(blockIdx.y);
    if (!sc.ok) return;
    int n0 = blockIdx.x * BN;

    uint32_t fullb = sb + BAR_OFF;
    uint32_t emptyb = sb + BAR_OFF + 32;
    if (tid == 0) {
        #pragma unroll
        for (int s = 0; s < STAGES; s++) {
            mbar_init(fullb + 8 * s, 256);
            mbar_init(emptyb + 8 * s, 8);
        }
    }
    __syncthreads();

    int arow = tid >> 1;
    const __half* a_src = g_h + (size_t)(sc.pbase + arow) * HID + (tid & 1) * 16;  // pad rows cover overrun
    uint32_t a_dst = sb + (arow * ASTRH + (tid & 1) * 16) * 2;
    const __half* WD = g_wdn + (size_t)sc.e * DIMX * HID;
    const __half* b_src = WD + (size_t)(n0 + arow) * HID + (tid & 1) * 16;
    uint32_t b_dst = sb + ((BM + arow) * ASTRH + (tid & 1) * 16) * 2;

    auto load_tile = [&](int ti, int st) {
        uint32_t so = (uint32_t)st * STG_B;
        const __half* ap = a_src + ti * BK;
        const __half* bp = b_src + ti * BK;
        cp16(a_dst + so, ap);
        cp16(a_dst + so + 16, ap + 8);
        cp16(b_dst + so, bp);
        cp16(b_dst + so + 16, bp + 8);
    };

    #pragma unroll
    for (int ti = 0; ti < 3; ti++) {
        load_tile(ti, ti);
        cp_arrive(fullb + 8 * ti);
    }

    float acc[4][4][4] = {};
    int wm = (wid >> 2) * 64, wq = wid & 3;
    uint32_t a_off = ((wm + (lane & 15)) * ASTRH + (lane >> 4) * 8) * 2;
    uint32_t b_off = ((BM + wq * 32 + (lane & 7)) * ASTRH + ((lane >> 3) & 1) * 8) * 2;

    for (int kt = 0; kt < KTD; kt++) {
        int s = kt & 3;
        mbar_wait(fullb + 8 * s, (kt >> 2) & 1);
        uint32_t Sb = sb + (uint32_t)s * STG_B;
        #pragma unroll
        for (int ks = 0; ks < 2; ks++) {
            uint32_t a[4][4];
            #pragma unroll
            for (int mt = 0; mt < 4; mt++)
                ldsm_x4(a[mt], Sb + a_off + mt * (16 * ASTRH * 2) + ks * 32);
            #pragma unroll
            for (int nt = 0; nt < 4; nt++) {
                uint32_t b0, b1;
                ldsm_x2(b0, b1, Sb + b_off + nt * (8 * ASTRH * 2) + ks * 32);
                #pragma unroll
                for (int mt = 0; mt < 4; mt++)
                    mma_f16(acc[mt][nt], a[mt], b0, b1);
            }
        }
        if (lane == 0) mbar_arrive(emptyb + 8 * s);
        int ti = kt + 3;
        if (ti < KTD) {
            int s2 = ti & 3;
            if (ti >= 4) mbar_wait(emptyb + 8 * s2, ((ti >> 2) - 1) & 1);
            load_tile(ti, s2);
            cp_arrive(fullb + 8 * s2);
        }
    }

    #pragma unroll
    for (int mt = 0; mt < 4; mt++) {
        #pragma unroll
        for (int hf = 0; hf < 2; hf++) {
            int r = wm + mt * 16 + g + hf * 8;
            if (r < sc.valid) {
                float* orow = g_down + (size_t)(sc.pbase + r) * DIMX + n0;
                #pragma unroll
                for (int nt = 0; nt < 4; nt++) {
                    int cc = wq * 32 + nt * 8 + 2 * tg;
                    float2 v;
                    v.x = acc[mt][nt][hf * 2]     * IWSCALE;
                    v.y = acc[mt][nt][hf * 2 + 1] * IWSCALE;
                    *(float2*)(orow + cc) = v;
                }
            }
        }
    }
}

// ---------------- kernel 6: combine out = x + w0*down[p0] + w1*down[p1] ----------------
__global__ void k_combine(const float* __restrict__ x, float* __restrict__ out) {
    int t = blockIdx.x, tid = threadIdx.x;
    int e0 = g_se[2 * t], j0 = g_sj[2 * t];
    int e1 = g_se[2 * t + 1], j1 = g_sj[2 * t + 1];
    float w0 = g_sw[2 * t], w1 = g_sw[2 * t + 1];
    int off0 = 0, off1 = 0;
    #pragma unroll
    for (int i = 0; i < 8; i++) {
        int ci = __ldg(&g_cnt[i]);
        if (i < e0) off0 += ci;
        if (i < e1) off1 += ci;
    }
    int p0 = off0 + j0, p1 = off1 + j1;
    const float4* x4 = (const float4*)(x + (size_t)t * DIMX);
    const float4* d0 = (const float4*)(g_down + (size_t)p0 * DIMX);
    const float4* d1 = (const float4*)(g_down + (size_t)p1 * DIMX);
    float4 a = x4[tid], u = d0[tid], v = d1[tid];
    float4 o;
    o.x = a.x + w0 * u.x + w1 * v.x;
    o.y = a.y + w0 * u.y + w1 * v.y;
    o.z = a.z + w0 * u.z + w1 * v.z;
    o.w = a.w + w0 * u.w + w1 * v.w;
    ((float4*)(out + (size_t)t * DIMX))[tid] = o;
}

// ---------------- launch ----------------
extern "C" void kernel_launch(void* const* d_in, const int* in_sizes, int n_in,
                              void* d_out, int out_size) {
    const float* x     = (const float*)d_in[0];
    const float* scale = (const float*)d_in[1];
    const float* wr    = (const float*)d_in[2];
    const float* wu    = (const float*)d_in[3];
    const float* wd    = (const float*)d_in[4];
    float* out = (float*)d_out;

    cudaFuncSetAttribute(k_up,   cudaFuncAttributeMaxDynamicSharedMemorySize, SMEM_TOT);
    cudaFuncSetAttribute(k_down, cudaFuncAttributeMaxDynamicSharedMemorySize, SMEM_TOT);

    k_zero<<<1, 32>>>();
    k_prep<<<2048, 256>>>(wu, wd);
    k_rms_router<<<M_TOK, 256>>>(x, scale, wr);
    // grid: x = n-tile (fast: a wave shares A row-tile, keeps B in L2), y = row-tile (264 >= 263 worst case)
    k_up  <<<dim3(HID / 64, 264), 256, SMEM_TOT>>>();    // (32, 264)
    k_down<<<dim3(DIMX / BN, 264), 256, SMEM_TOT>>>();   // (8, 264)
    k_combine<<<M_TOK, 256>>>(x, out);
}